// round 2
// baseline (speedup 1.0000x reference)
#include <cuda_runtime.h>
#include <cstdint>

// ---------------- problem constants ----------------
#define T     2048
#define DIN   512
#define DOUT  512
#define KF    24
#define NC    48          // 2 * KF  (plus / minus channels)
#define KU    3
#define BT    128         // time block
#define NBLK  16          // T / BT
#define SPLIT 5           // deterministic split-K for conv GEMM

// ---------------- device scratch (no allocations allowed) ----------------
__device__ float g_Z[(size_t)NC * T * DOUT];        // 48*2048*512 fp32 = 201 MB
__device__ float g_part[(size_t)SPLIT * T * DOUT];  // split-K partials
__device__ float g_phiT[NC * T];                    // phi transposed + (-1)^s for minus
__device__ float g_MT[KU * DIN * DOUT];             // M transposed: [tau][d][o]

// ---------------- helpers ----------------
__device__ __forceinline__ float f2tf32(float v) {
    uint32_t u;
    asm("cvt.rna.tf32.f32 %0, %1;" : "=r"(u) : "f"(v));
    return __uint_as_float(u);
}

__device__ __forceinline__ void mma_tf32(float* c, const uint32_t* a, const uint32_t* b) {
    asm("mma.sync.aligned.m16n8k8.row.col.f32.tf32.tf32.f32 "
        "{%0,%1,%2,%3}, {%4,%5,%6,%7}, {%8,%9}, {%0,%1,%2,%3};"
        : "+f"(c[0]), "+f"(c[1]), "+f"(c[2]), "+f"(c[3])
        : "r"(a[0]), "r"(a[1]), "r"(a[2]), "r"(a[3]),
          "r"(b[0]), "r"(b[1]));
}

// ---------------- prep: phiT and MT ----------------
__global__ void prep_kernel(const float* __restrict__ phi, const float* __restrict__ M) {
    int idx = blockIdx.x * blockDim.x + threadIdx.x;
    if (idx < NC * T) {
        int c = idx / T, s = idx - c * T;
        int k = (c < KF) ? c : c - KF;
        float v = phi[s * KF + k];
        if (c >= KF && (s & 1)) v = -v;     // phi_minus[s] = (-1)^s phi[s]
        g_phiT[idx] = v;
    }
    int r = idx - NC * T;
    if (r >= 0 && r < KU * DIN * DOUT) {
        int tau = r / (DIN * DOUT);
        int rem = r - tau * (DIN * DOUT);
        int d = rem / DOUT, o = rem - d * DOUT;
        g_MT[r] = M[((size_t)o * DIN + d) * KU + tau];
    }
}

// ---------------- GEMM1: Z[c][t][o] = sum_d x[t,d] * M_c[k][d][o] ----------------
__global__ void __launch_bounds__(256) gemm1_kernel(
    const float* __restrict__ x, const float* __restrict__ Mp, const float* __restrict__ Mm)
{
    __shared__ float As[32][BT + 4];   // [k][m]
    __shared__ float Bs[32][BT + 4];   // [k][n]

    const int tTile = blockIdx.x, oTile = blockIdx.y, c = blockIdx.z;
    const float* W = (c < KF) ? (Mp + (size_t)c * DIN * DOUT)
                              : (Mm + (size_t)(c - KF) * DIN * DOUT);
    const int t0 = tTile * BT, n0 = oTile * BT;
    const int tid = threadIdx.x;
    const int warp = tid >> 5, lane = tid & 31;
    const int wm = warp >> 2, wn = warp & 3;          // 2x4 warps, warp tile 64x32
    const int mbase = wm * 64, nbase = wn * 32;
    const int tg = lane >> 2, tig = lane & 3;

    float acc[4][4][4];
    #pragma unroll
    for (int a0 = 0; a0 < 4; ++a0)
        #pragma unroll
        for (int b0 = 0; b0 < 4; ++b0)
            #pragma unroll
            for (int e = 0; e < 4; ++e) acc[a0][b0][e] = 0.f;

    for (int kt = 0; kt < DIN; kt += 32) {
        #pragma unroll
        for (int it = 0; it < 4; ++it) {            // A: x tile 128x32 -> transposed smem
            int fl = tid + it * 256;
            int r = fl >> 3;
            int c4 = (fl & 7) << 2;
            float4 v = *(const float4*)(x + (size_t)(t0 + r) * DIN + kt + c4);
            As[c4 + 0][r] = f2tf32(v.x); As[c4 + 1][r] = f2tf32(v.y);
            As[c4 + 2][r] = f2tf32(v.z); As[c4 + 3][r] = f2tf32(v.w);
        }
        #pragma unroll
        for (int it = 0; it < 4; ++it) {            // B: W tile 32x128
            int fl = tid + it * 256;
            int rr = fl >> 5;
            int o4 = (fl & 31) << 2;
            float4 v = *(const float4*)(W + (size_t)(kt + rr) * DOUT + n0 + o4);
            float4 w = make_float4(f2tf32(v.x), f2tf32(v.y), f2tf32(v.z), f2tf32(v.w));
            *(float4*)&Bs[rr][o4] = w;
        }
        __syncthreads();
        #pragma unroll
        for (int ks = 0; ks < 32; ks += 8) {
            uint32_t af[4][4], bf[4][2];
            #pragma unroll
            for (int mf = 0; mf < 4; ++mf) {
                int r0 = mbase + mf * 16;
                af[mf][0] = __float_as_uint(As[ks + tig][r0 + tg]);
                af[mf][1] = __float_as_uint(As[ks + tig][r0 + tg + 8]);
                af[mf][2] = __float_as_uint(As[ks + tig + 4][r0 + tg]);
                af[mf][3] = __float_as_uint(As[ks + tig + 4][r0 + tg + 8]);
            }
            #pragma unroll
            for (int nf = 0; nf < 4; ++nf) {
                int c0 = nbase + nf * 8;
                bf[nf][0] = __float_as_uint(Bs[ks + tig][c0 + tg]);
                bf[nf][1] = __float_as_uint(Bs[ks + tig + 4][c0 + tg]);
            }
            #pragma unroll
            for (int mf = 0; mf < 4; ++mf)
                #pragma unroll
                for (int nf = 0; nf < 4; ++nf)
                    mma_tf32(acc[mf][nf], af[mf], bf[nf]);
        }
        __syncthreads();
    }

    float* Zc = g_Z + (size_t)c * T * DOUT;
    #pragma unroll
    for (int mf = 0; mf < 4; ++mf) {
        int r0 = t0 + mbase + mf * 16 + tg;
        #pragma unroll
        for (int nf = 0; nf < 4; ++nf) {
            int c0 = n0 + nbase + nf * 8 + tig * 2;
            Zc[(size_t)r0 * DOUT + c0]           = acc[mf][nf][0];
            Zc[(size_t)r0 * DOUT + c0 + 1]       = acc[mf][nf][1];
            Zc[(size_t)(r0 + 8) * DOUT + c0]     = acc[mf][nf][2];
            Zc[(size_t)(r0 + 8) * DOUT + c0 + 1] = acc[mf][nf][3];
        }
    }
}

// -------- GEMM2: out[t,o] = sum_c (phi_c (*) Z_c)[t,o] + AR, blocked Toeplitz --------
__global__ void __launch_bounds__(256) gemm2_kernel(const float* __restrict__ x)
{
    __shared__ float Bs[32][BT + 4];
    __shared__ float Asm[32][BT + 4];   // AR A tile (transposed x)
    __shared__ float seg[160];          // phi segment for Toeplitz tile

    const int bx = blockIdx.x;
    const int i = bx >> 2, ot = bx & 3, sp = blockIdx.y;
    const int t0 = i * BT, n0 = ot * BT;
    const int tid = threadIdx.x;
    const int warp = tid >> 5, lane = tid & 31;
    const int wm = warp >> 2, wn = warp & 3;
    const int mbase = wm * 64, nbase = wn * 32;
    const int tg = lane >> 2, tig = lane & 3;

    float acc[4][4][4];
    #pragma unroll
    for (int a0 = 0; a0 < 4; ++a0)
        #pragma unroll
        for (int b0 = 0; b0 < 4; ++b0)
            #pragma unroll
            for (int e = 0; e < 4; ++e) acc[a0][b0][e] = 0.f;

    const int per = (i + 1) * 4;        // K=32 chunks per channel
    const int nconv = NC * per;
    const int ntot = nconv + KU * (DIN / 32);

    for (int q = sp; q < ntot; q += SPLIT) {
        const bool isconv = (q < nconv);
        if (isconv) {
            int cch = q / per;
            int rem = q - cch * per;
            int j = rem >> 2;
            int ks0 = (rem & 3) << 5;
            // B tile: Z_c rows [j*128+ks0 .. +31], cols [n0..n0+127]
            const float* Zc = g_Z + ((size_t)cch * T + j * BT + ks0) * DOUT + n0;
            #pragma unroll
            for (int it = 0; it < 4; ++it) {
                int fl = tid + it * 256;
                int rr = fl >> 5, o4 = (fl & 31) << 2;
                float4 v = *(const float4*)(Zc + (size_t)rr * DOUT + o4);
                float4 w = make_float4(f2tf32(v.x), f2tf32(v.y), f2tf32(v.z), f2tf32(v.w));
                *(float4*)&Bs[rr][o4] = w;
            }
            // phi segment: P[a][kk] = phiT[c][(i-j)*128 + a - (ks0+kk)] = seg[a-kk+31]
            int sbase = (i - j) * BT - ks0 - 31;
            for (int u = tid; u < 160; u += 256) {
                int s = sbase + u;
                seg[u] = (s >= 0 && s < T) ? f2tf32(g_phiT[cch * T + s]) : 0.f;
            }
        } else {
            int r = q - nconv;
            int tau = r >> 4;
            int ks0 = (r & 15) << 5;
            const float* Wt = g_MT + ((size_t)tau * DIN + ks0) * DOUT + n0;
            #pragma unroll
            for (int it = 0; it < 4; ++it) {
                int fl = tid + it * 256;
                int rr = fl >> 5, o4 = (fl & 31) << 2;
                float4 v = *(const float4*)(Wt + (size_t)rr * DOUT + o4);
                float4 w = make_float4(f2tf32(v.x), f2tf32(v.y), f2tf32(v.z), f2tf32(v.w));
                *(float4*)&Bs[rr][o4] = w;
            }
            #pragma unroll
            for (int it = 0; it < 4; ++it) {   // A tile: x rows shifted by tau, transposed
                int fl = tid + it * 256;
                int a = fl >> 3;
                int c4 = (fl & 7) << 2;
                int row = t0 + a - tau;
                float4 v = (row >= 0)
                    ? *(const float4*)(x + (size_t)row * DIN + ks0 + c4)
                    : make_float4(0.f, 0.f, 0.f, 0.f);
                Asm[c4 + 0][a] = f2tf32(v.x); Asm[c4 + 1][a] = f2tf32(v.y);
                Asm[c4 + 2][a] = f2tf32(v.z); Asm[c4 + 3][a] = f2tf32(v.w);
            }
        }
        __syncthreads();

        if (isconv) {
            #pragma unroll
            for (int ks = 0; ks < 32; ks += 8) {
                uint32_t af[4][4], bf[4][2];
                #pragma unroll
                for (int mf = 0; mf < 4; ++mf) {
                    int u0 = mbase + mf * 16 + tg - ks - tig + 31;
                    af[mf][0] = __float_as_uint(seg[u0]);
                    af[mf][1] = __float_as_uint(seg[u0 + 8]);
                    af[mf][2] = __float_as_uint(seg[u0 - 4]);
                    af[mf][3] = __float_as_uint(seg[u0 + 4]);
                }
                #pragma unroll
                for (int nf = 0; nf < 4; ++nf) {
                    int c0 = nbase + nf * 8;
                    bf[nf][0] = __float_as_uint(Bs[ks + tig][c0 + tg]);
                    bf[nf][1] = __float_as_uint(Bs[ks + tig + 4][c0 + tg]);
                }
                #pragma unroll
                for (int mf = 0; mf < 4; ++mf)
                    #pragma unroll
                    for (int nf = 0; nf < 4; ++nf)
                        mma_tf32(acc[mf][nf], af[mf], bf[nf]);
            }
        } else {
            #pragma unroll
            for (int ks = 0; ks < 32; ks += 8) {
                uint32_t af[4][4], bf[4][2];
                #pragma unroll
                for (int mf = 0; mf < 4; ++mf) {
                    int r0 = mbase + mf * 16;
                    af[mf][0] = __float_as_uint(Asm[ks + tig][r0 + tg]);
                    af[mf][1] = __float_as_uint(Asm[ks + tig][r0 + tg + 8]);
                    af[mf][2] = __float_as_uint(Asm[ks + tig + 4][r0 + tg]);
                    af[mf][3] = __float_as_uint(Asm[ks + tig + 4][r0 + tg + 8]);
                }
                #pragma unroll
                for (int nf = 0; nf < 4; ++nf) {
                    int c0 = nbase + nf * 8;
                    bf[nf][0] = __float_as_uint(Bs[ks + tig][c0 + tg]);
                    bf[nf][1] = __float_as_uint(Bs[ks + tig + 4][c0 + tg]);
                }
                #pragma unroll
                for (int mf = 0; mf < 4; ++mf)
                    #pragma unroll
                    for (int nf = 0; nf < 4; ++nf)
                        mma_tf32(acc[mf][nf], af[mf], bf[nf]);
            }
        }
        __syncthreads();
    }

    float* P = g_part + (size_t)sp * T * DOUT;
    #pragma unroll
    for (int mf = 0; mf < 4; ++mf) {
        int r0 = t0 + mbase + mf * 16 + tg;
        #pragma unroll
        for (int nf = 0; nf < 4; ++nf) {
            int c0 = n0 + nbase + nf * 8 + tig * 2;
            P[(size_t)r0 * DOUT + c0]           = acc[mf][nf][0];
            P[(size_t)r0 * DOUT + c0 + 1]       = acc[mf][nf][1];
            P[(size_t)(r0 + 8) * DOUT + c0]     = acc[mf][nf][2];
            P[(size_t)(r0 + 8) * DOUT + c0 + 1] = acc[mf][nf][3];
        }
    }
}

// ---------------- reduce split-K partials ----------------
__global__ void reduce_kernel(float* __restrict__ out) {
    size_t idx = (size_t)(blockIdx.x * blockDim.x + threadIdx.x) * 4;
    float4 s = make_float4(0.f, 0.f, 0.f, 0.f);
    #pragma unroll
    for (int p = 0; p < SPLIT; ++p) {
        float4 v = *(const float4*)(g_part + (size_t)p * T * DOUT + idx);
        s.x += v.x; s.y += v.y; s.z += v.z; s.w += v.w;
    }
    *(float4*)(out + idx) = s;
}

// ---------------- entry ----------------
extern "C" void kernel_launch(void* const* d_in, const int* in_sizes, int n_in,
                              void* d_out, int out_size) {
    const float* x   = (const float*)d_in[0];
    const float* phi = (const float*)d_in[1];
    const float* M   = (const float*)d_in[2];
    const float* Mp  = (const float*)d_in[3];
    const float* Mm  = (const float*)d_in[4];
    float* out = (float*)d_out;

    prep_kernel<<<(NC * T + KU * DIN * DOUT + 255) / 256, 256>>>(phi, M);
    gemm1_kernel<<<dim3(NBLK, 4, NC), 256>>>(x, Mp, Mm);
    gemm2_kernel<<<dim3(NBLK * 4, SPLIT), 256>>>(x);
    reduce_kernel<<<(T * DOUT / 4 + 255) / 256, 256>>>(out);
}

// round 4
// speedup vs baseline: 1.6004x; 1.6004x over previous
#include <cuda_runtime.h>
#include <cuda_fp16.h>
#include <cstdint>

// ---------------- problem constants ----------------
#define T     2048
#define DIN   512
#define DOUT  512
#define KF    24
#define NC    48
#define KU    3
#define SPLIT 5
#define NT    256

// smem: 4-stage ring, each stage = A(128x40 half) + B(128x40 half) = 10240+10240
#define PITCH   40
#define TILE_B  10240
#define STRIDE  20480
#define SMEM_SZ (4 * STRIDE)

// ---------------- device scratch ----------------
__device__ __half g_Zh[(size_t)NC * DOUT * T];      // [c][o][t]  100 MB
__device__ float  g_part[(size_t)SPLIT * T * DOUT]; // split-K partials (f32)
__device__ __half g_phiH[NC * T];                   // minus channel has (-1)^lag baked in
__device__ __half g_MTh[(size_t)KU * DOUT * DIN];   // [tau][o][d]
__device__ __half g_WTh[(size_t)NC * DOUT * DIN];   // [c][o][d]
__device__ __half g_xh[(size_t)T * DIN];            // x in fp16

// ---------------- helpers ----------------
__device__ __forceinline__ uint32_t s2u(const void* p) {
    uint32_t a;
    asm("{ .reg .u64 t; cvta.to.shared.u64 t, %1; cvt.u32.u64 %0, t; }" : "=r"(a) : "l"(p));
    return a;
}
__device__ __forceinline__ void cp16(uint32_t dst, const void* src, uint32_t pbytes) {
    asm volatile("cp.async.cg.shared.global [%0], [%1], 16, %2;"
        :: "r"(dst), "l"(src), "r"(pbytes) : "memory");
}
#define CP_COMMIT() asm volatile("cp.async.commit_group;" ::: "memory")
#define CP_WAIT(N)  asm volatile("cp.async.wait_group %0;" :: "n"(N) : "memory")

__device__ __forceinline__ void mma168(float* c, const uint32_t* a, const uint32_t* b) {
    asm volatile("mma.sync.aligned.m16n8k16.row.col.f32.f16.f16.f32 "
        "{%0,%1,%2,%3}, {%4,%5,%6,%7}, {%8,%9}, {%0,%1,%2,%3};"
        : "+f"(c[0]), "+f"(c[1]), "+f"(c[2]), "+f"(c[3])
        : "r"(a[0]), "r"(a[1]), "r"(a[2]), "r"(a[3]), "r"(b[0]), "r"(b[1]));
}

// one K=32 chunk for the whole 128x128 block tile (warp tile 64x32)
__device__ __forceinline__ void compute_chunk(
    const char* smem, int st, int mbase, int nbase, int lg, int t4, float acc[4][4][4])
{
    const __half* As = (const __half*)(smem + st * STRIDE);
    const __half* Bs = (const __half*)(smem + st * STRIDE + TILE_B);
    #pragma unroll
    for (int kf = 0; kf < 2; ++kf) {
        uint32_t a[4][4], b[4][2];
        #pragma unroll
        for (int mf = 0; mf < 4; ++mf) {
            const __half* p = As + (mbase + mf * 16 + lg) * PITCH + kf * 16 + 2 * t4;
            a[mf][0] = *(const uint32_t*)(p);
            a[mf][1] = *(const uint32_t*)(p + 8 * PITCH);
            a[mf][2] = *(const uint32_t*)(p + 8);
            a[mf][3] = *(const uint32_t*)(p + 8 * PITCH + 8);
        }
        #pragma unroll
        for (int nf = 0; nf < 4; ++nf) {
            const __half* p = Bs + (nbase + nf * 8 + lg) * PITCH + kf * 16 + 2 * t4;
            b[nf][0] = *(const uint32_t*)(p);
            b[nf][1] = *(const uint32_t*)(p + 8);
        }
        #pragma unroll
        for (int mf = 0; mf < 4; ++mf)
            #pragma unroll
            for (int nf = 0; nf < 4; ++nf)
                mma168(acc[mf][nf], a[mf], b[nf]);
    }
}

// ---------------- prep ----------------
__global__ void prep_h(const float* __restrict__ x, const float* __restrict__ phi,
                       const float* __restrict__ M) {
    int idx = blockIdx.x * 256 + threadIdx.x;
    if (idx < T * DIN) g_xh[idx] = __float2half_rn(x[idx]);
    int p = idx - T * DIN;
    if (p >= 0 && p < NC * T) {
        int c = p / T, s = p - c * T;
        int k = (c < KF) ? c : c - KF;
        float v = phi[s * KF + k];
        if (c >= KF && (s & 1)) v = -v;
        g_phiH[p] = __float2half_rn(v);
    }
    int m = idx - T * DIN - NC * T;
    if (m >= 0 && m < KU * DOUT * DIN) {
        int tau = m / (DOUT * DIN);
        int rm = m - tau * (DOUT * DIN);
        int o = rm / DIN, d = rm - o * DIN;
        g_MTh[m] = __float2half_rn(M[((size_t)o * DIN + d) * KU + tau]);
    }
}

__global__ void prep_wth(const float* __restrict__ Mp, const float* __restrict__ Mm) {
    __shared__ float t[32][33];
    int c = blockIdx.z;
    const float* W = (c < KF) ? Mp + (size_t)c * DIN * DOUT
                              : Mm + (size_t)(c - KF) * DIN * DOUT;   // [d][o]
    int d0 = blockIdx.x * 32, o0 = blockIdx.y * 32;
    int tx = threadIdx.x, ty = threadIdx.y;
    #pragma unroll
    for (int r = 0; r < 32; r += 8)
        t[ty + r][tx] = W[(size_t)(d0 + ty + r) * DOUT + o0 + tx];
    __syncthreads();
    __half* dst = g_WTh + (size_t)c * DOUT * DIN;
    #pragma unroll
    for (int r = 0; r < 32; r += 8)
        dst[(size_t)(o0 + ty + r) * DIN + d0 + tx] = __float2half_rn(t[tx][ty + r]);
}

// ------- GEMM1: Zh[c][o0+m][t0+n] = sum_d WTh[c][o][d] * xh[t][d] -------
__global__ void __launch_bounds__(NT) gemm1_kernel() {
    extern __shared__ char smem[];
    const uint32_t sb = s2u(smem);
    const int tid = threadIdx.x;
    const int warp = tid >> 5, lane = tid & 31;
    const int lg = lane >> 2, t4 = lane & 3;
    const int mbase = (warp >> 2) * 64, nbase = (warp & 3) * 32;
    const int t0 = blockIdx.x * 128, o0 = blockIdx.y * 128, c = blockIdx.z;

    const __half* Asrc = g_WTh + ((size_t)c * DOUT + o0) * DIN;
    const __half* Bsrc = g_xh + (size_t)t0 * DIN;

    float acc[4][4][4];
    #pragma unroll
    for (int i = 0; i < 4; ++i)
        #pragma unroll
        for (int j = 0; j < 4; ++j)
            #pragma unroll
            for (int e = 0; e < 4; ++e) acc[i][j][e] = 0.f;

    auto load = [&](int q) {
        int st = q & 3;
        uint32_t ab = sb + st * STRIDE, bb = ab + TILE_B;
        int kt0 = q * 32;
        #pragma unroll
        for (int it = 0; it < 2; ++it) {
            int g = tid + it * NT;
            int r = g >> 2, c16 = g & 3;
            cp16(ab + r * 80 + c16 * 16, Asrc + (size_t)r * DIN + kt0 + c16 * 8, 16);
            cp16(bb + r * 80 + c16 * 16, Bsrc + (size_t)r * DIN + kt0 + c16 * 8, 16);
        }
        CP_COMMIT();
    };

    const int NCH = DIN / 32;   // 16
    load(0); load(1);
    for (int k = 0; k < NCH; k++) {
        if (k + 2 < NCH) { load(k + 2); CP_WAIT(2); }
        else if (k + 1 < NCH) { CP_WAIT(1); }
        else { CP_WAIT(0); }
        __syncthreads();
        compute_chunk(smem, k & 3, mbase, nbase, lg, t4, acc);
    }

    // epilogue: C[m=o][n=t] -> g_Zh[c][o][t] as half2
    #pragma unroll
    for (int mf = 0; mf < 4; ++mf) {
        int r0 = o0 + mbase + mf * 16 + lg;
        #pragma unroll
        for (int nf = 0; nf < 4; ++nf) {
            int cc = t0 + nbase + nf * 8 + 2 * t4;
            __half2 v01 = __floats2half2_rn(acc[mf][nf][0], acc[mf][nf][1]);
            __half2 v23 = __floats2half2_rn(acc[mf][nf][2], acc[mf][nf][3]);
            *(__half2*)(g_Zh + ((size_t)c * DOUT + r0) * T + cc)     = v01;
            *(__half2*)(g_Zh + ((size_t)c * DOUT + r0 + 8) * T + cc) = v23;
        }
    }
}

// -- GEMM2: out[t,o] = sum_{c,s<=t} phi_c[t-s]*Zh[c][o][s] + AR; Toeplitz A --
__global__ void __launch_bounds__(NT) gemm2_kernel() {
    extern __shared__ char smem[];
    const uint32_t sb = s2u(smem);
    const int tid = threadIdx.x;
    const int warp = tid >> 5, lane = tid & 31;
    const int lg = lane >> 2, t4 = lane & 3;
    const int mbase = (warp >> 2) * 64, nbase = (warp & 3) * 32;
    const int bx = blockIdx.x;
    const int i = 15 - (bx >> 2), ot = bx & 3, sp = blockIdx.y;   // heavy first
    const int t0 = i * 128, o0 = ot * 128;
    const int per = (i + 1) * 4, nconv = NC * per, ntot = nconv + KU * (DIN / 32);
    const int NCH = (ntot - sp + SPLIT - 1) / SPLIT;

    float acc[4][4][4];
    #pragma unroll
    for (int a0 = 0; a0 < 4; ++a0)
        #pragma unroll
        for (int b0 = 0; b0 < 4; ++b0)
            #pragma unroll
            for (int e = 0; e < 4; ++e) acc[a0][b0][e] = 0.f;

    auto load = [&](int idx) {
        int q = sp + idx * SPLIT;
        int st = idx & 3;
        uint32_t ab = sb + st * STRIDE, bb = ab + TILE_B;
        if (q < nconv) {
            int cch = q / per, rm = q - cch * per;
            int j = rm >> 2, ks0 = (rm & 3) << 5;
            const __half* Bsrc = g_Zh + ((size_t)cch * DOUT + o0) * T + j * 128 + ks0;
            #pragma unroll
            for (int it = 0; it < 2; ++it) {
                int g = tid + it * NT;
                int r = g >> 2, c16 = g & 3;
                cp16(bb + r * 80 + c16 * 16, Bsrc + (size_t)r * T + c16 * 8, 16);
            }
            CP_COMMIT();
            // Toeplitz A in smem: A[m][k] = phiH[c][base + m - k], 0 if idx<0
            const __half* ph = g_phiH + cch * T;
            __half* As = (__half*)(smem + st * STRIDE);
            int base = (i - j) * 128 - ks0;
            #pragma unroll
            for (int it = 0; it < 2; ++it) {
                int g = tid + it * NT;
                int row = g >> 2, c0 = (g & 3) * 8;
                int idx0 = base + row - c0;
                #pragma unroll
                for (int kk = 0; kk < 8; kk += 2) {
                    int i0 = idx0 - kk;
                    __half v0 = (i0 >= 0)     ? ph[i0]     : __float2half_rn(0.f);
                    __half v1 = (i0 - 1 >= 0) ? ph[i0 - 1] : __float2half_rn(0.f);
                    *(__half2*)(As + row * PITCH + c0 + kk) = __halves2half2(v0, v1);
                }
            }
        } else {
            int r = q - nconv, tau = r >> 4, ks0 = (r & 15) << 5;
            const __half* Bsrc = g_MTh + ((size_t)tau * DOUT + o0) * DIN + ks0;
            #pragma unroll
            for (int it = 0; it < 2; ++it) {
                int g = tid + it * NT;
                int rr = g >> 2, c16 = g & 3;
                cp16(bb + rr * 80 + c16 * 16, Bsrc + (size_t)rr * DIN + c16 * 8, 16);
                int trow = t0 + rr - tau;
                const __half* As = g_xh + (size_t)(trow < 0 ? 0 : trow) * DIN + ks0 + c16 * 8;
                cp16(ab + rr * 80 + c16 * 16, As, trow >= 0 ? 16u : 0u);
            }
            CP_COMMIT();
        }
    };

    load(0);
    if (NCH > 1) load(1);
    for (int k = 0; k < NCH; k++) {
        if (k + 2 < NCH) { load(k + 2); CP_WAIT(2); }
        else if (k + 1 < NCH) { CP_WAIT(1); }
        else { CP_WAIT(0); }
        __syncthreads();
        compute_chunk(smem, k & 3, mbase, nbase, lg, t4, acc);
    }

    // epilogue: C[m=t][n=o] -> g_part[sp][t][o] (f32)
    float* P = g_part + (size_t)sp * T * DOUT;
    #pragma unroll
    for (int mf = 0; mf < 4; ++mf) {
        int r0 = t0 + mbase + mf * 16 + lg;
        #pragma unroll
        for (int nf = 0; nf < 4; ++nf) {
            int cc = o0 + nbase + nf * 8 + 2 * t4;
            *(float2*)(P + (size_t)r0 * DOUT + cc)       = make_float2(acc[mf][nf][0], acc[mf][nf][1]);
            *(float2*)(P + (size_t)(r0 + 8) * DOUT + cc) = make_float2(acc[mf][nf][2], acc[mf][nf][3]);
        }
    }
}

// ---------------- reduce split-K partials ----------------
__global__ void reduce_kernel(float* __restrict__ out) {
    size_t idx = (size_t)(blockIdx.x * blockDim.x + threadIdx.x) * 4;
    float4 s = make_float4(0.f, 0.f, 0.f, 0.f);
    #pragma unroll
    for (int p = 0; p < SPLIT; ++p) {
        float4 v = *(const float4*)(g_part + (size_t)p * T * DOUT + idx);
        s.x += v.x; s.y += v.y; s.z += v.z; s.w += v.w;
    }
    *(float4*)(out + idx) = s;
}

// ---------------- entry ----------------
extern "C" void kernel_launch(void* const* d_in, const int* in_sizes, int n_in,
                              void* d_out, int out_size) {
    const float* x   = (const float*)d_in[0];
    const float* phi = (const float*)d_in[1];
    const float* M   = (const float*)d_in[2];
    const float* Mp  = (const float*)d_in[3];
    const float* Mm  = (const float*)d_in[4];
    float* out = (float*)d_out;

    cudaFuncSetAttribute(gemm1_kernel, cudaFuncAttributeMaxDynamicSharedMemorySize, SMEM_SZ);
    cudaFuncSetAttribute(gemm2_kernel, cudaFuncAttributeMaxDynamicSharedMemorySize, SMEM_SZ);

    int tot = T * DIN + NC * T + KU * DOUT * DIN;
    prep_h<<<(tot + 255) / 256, 256>>>(x, phi, M);
    prep_wth<<<dim3(16, 16, 48), dim3(32, 8)>>>(Mp, Mm);
    gemm1_kernel<<<dim3(16, 4, NC), NT, SMEM_SZ>>>();
    gemm2_kernel<<<dim3(64, SPLIT), NT, SMEM_SZ>>>();
    reduce_kernel<<<(T * DOUT / 4 + 255) / 256, 256>>>(out);
}

// round 5
// speedup vs baseline: 1.6947x; 1.0589x over previous
#include <cuda_runtime.h>
#include <cuda_fp16.h>
#include <cstdint>

// ---------------- problem constants ----------------
#define T     2048
#define DIN   512
#define DOUT  512
#define KF    24
#define NC    48
#define KU    3
#define NT    256
#define SPLANES 16

// smem: 3-stage ring, each stage = A(128x40 half) + B(128x40 half)
#define PITCH   40
#define TILE_B  10240
#define STRIDE  20480
#define SMEM_SZ (3 * STRIDE)

// ---------------- device scratch ----------------
__device__ __half g_Zh[(size_t)NC * DOUT * T];        // [c][o][t]  100 MB
__device__ float  g_part[(size_t)SPLANES * T * DOUT]; // split-K partials (f32)
__device__ __half g_phiH[NC * T];                     // minus channel has (-1)^lag baked in
__device__ __half g_MTh[(size_t)KU * DOUT * DIN];     // [tau][o][d]
__device__ __half g_WTh[(size_t)NC * DOUT * DIN];     // [c][o][d]
__device__ __half g_xh[(size_t)T * DIN];              // x in fp16

// ---------------- helpers ----------------
__device__ __forceinline__ uint32_t s2u(const void* p) {
    uint32_t a;
    asm("{ .reg .u64 t; cvta.to.shared.u64 t, %1; cvt.u32.u64 %0, t; }" : "=r"(a) : "l"(p));
    return a;
}
__device__ __forceinline__ void cp16(uint32_t dst, const void* src, uint32_t pbytes) {
    asm volatile("cp.async.cg.shared.global [%0], [%1], 16, %2;"
        :: "r"(dst), "l"(src), "r"(pbytes) : "memory");
}
#define CP_COMMIT() asm volatile("cp.async.commit_group;" ::: "memory")
#define CP_WAIT(N)  asm volatile("cp.async.wait_group %0;" :: "n"(N) : "memory")

__device__ __forceinline__ void mma168(float* c, const uint32_t* a, const uint32_t* b) {
    asm volatile("mma.sync.aligned.m16n8k16.row.col.f32.f16.f16.f32 "
        "{%0,%1,%2,%3}, {%4,%5,%6,%7}, {%8,%9}, {%0,%1,%2,%3};"
        : "+f"(c[0]), "+f"(c[1]), "+f"(c[2]), "+f"(c[3])
        : "r"(a[0]), "r"(a[1]), "r"(a[2]), "r"(a[3]), "r"(b[0]), "r"(b[1]));
}
__device__ __forceinline__ void ldm4(uint32_t& r0, uint32_t& r1, uint32_t& r2, uint32_t& r3,
                                     uint32_t addr) {
    asm volatile("ldmatrix.sync.aligned.m8n8.x4.shared.b16 {%0,%1,%2,%3}, [%4];"
        : "=r"(r0), "=r"(r1), "=r"(r2), "=r"(r3) : "r"(addr));
}

// one K=32 chunk for the 128x128 block tile; warp tile 64x32; ldmatrix feeds
__device__ __forceinline__ void compute_chunk(
    uint32_t sbase, int mbase, int nbase, uint32_t aoff, uint32_t boff, float acc[4][4][4])
{
    #pragma unroll
    for (int kf = 0; kf < 2; ++kf) {
        uint32_t b[4][2];
        #pragma unroll
        for (int nfp = 0; nfp < 2; ++nfp) {
            uint32_t addr = sbase + TILE_B + boff +
                            (uint32_t)(((nbase + nfp * 16) * PITCH + kf * 16) * 2);
            ldm4(b[2 * nfp][0], b[2 * nfp][1], b[2 * nfp + 1][0], b[2 * nfp + 1][1], addr);
        }
        #pragma unroll
        for (int mf = 0; mf < 4; ++mf) {
            uint32_t av[4];
            uint32_t addr = sbase + aoff +
                            (uint32_t)(((mbase + mf * 16) * PITCH + kf * 16) * 2);
            ldm4(av[0], av[1], av[2], av[3], addr);
            #pragma unroll
            for (int nf = 0; nf < 4; ++nf)
                mma168(acc[mf][nf], av, b[nf]);
        }
    }
}

// ---------------- prep ----------------
__global__ void prep_h(const float* __restrict__ x, const float* __restrict__ phi,
                       const float* __restrict__ M) {
    int idx = blockIdx.x * 256 + threadIdx.x;
    if (idx < T * DIN) g_xh[idx] = __float2half_rn(x[idx]);
    int p = idx - T * DIN;
    if (p >= 0 && p < NC * T) {
        int c = p / T, s = p - c * T;
        int k = (c < KF) ? c : c - KF;
        float v = phi[s * KF + k];
        if (c >= KF && (s & 1)) v = -v;
        g_phiH[p] = __float2half_rn(v);
    }
    int m = idx - T * DIN - NC * T;
    if (m >= 0 && m < KU * DOUT * DIN) {
        int tau = m / (DOUT * DIN);
        int rm = m - tau * (DOUT * DIN);
        int o = rm / DIN, d = rm - o * DIN;
        g_MTh[m] = __float2half_rn(M[((size_t)o * DIN + d) * KU + tau]);
    }
}

__global__ void prep_wth(const float* __restrict__ Mp, const float* __restrict__ Mm) {
    __shared__ float t[32][33];
    int c = blockIdx.z;
    const float* W = (c < KF) ? Mp + (size_t)c * DIN * DOUT
                              : Mm + (size_t)(c - KF) * DIN * DOUT;   // [d][o]
    int d0 = blockIdx.x * 32, o0 = blockIdx.y * 32;
    int tx = threadIdx.x, ty = threadIdx.y;
    #pragma unroll
    for (int r = 0; r < 32; r += 8)
        t[ty + r][tx] = W[(size_t)(d0 + ty + r) * DOUT + o0 + tx];
    __syncthreads();
    __half* dst = g_WTh + (size_t)c * DOUT * DIN;
    #pragma unroll
    for (int r = 0; r < 32; r += 8)
        dst[(size_t)(o0 + ty + r) * DIN + d0 + tx] = __float2half_rn(t[tx][ty + r]);
}

// ------- GEMM1: Zh[c][o0+m][t0+n] = sum_d WTh[c][o][d] * xh[t][d] -------
__global__ void __launch_bounds__(NT, 3) gemm1_kernel() {
    extern __shared__ char smem[];
    const uint32_t sb = s2u(smem);
    const int tid = threadIdx.x;
    const int warp = tid >> 5, lane = tid & 31;
    const int lg = lane >> 2, t4 = lane & 3;
    const int mbase = (warp >> 2) * 64, nbase = (warp & 3) * 32;
    const uint32_t aoff = (uint32_t)(((lane & 15) * PITCH + (lane >> 4) * 8) * 2);
    const uint32_t boff = (uint32_t)((((lane & 7) + ((lane >> 4) & 1) * 8) * PITCH +
                                      ((lane >> 3) & 1) * 8) * 2);
    const int t0 = blockIdx.x * 128, o0 = blockIdx.y * 128, c = blockIdx.z;

    const __half* Asrc = g_WTh + ((size_t)c * DOUT + o0) * DIN;
    const __half* Bsrc = g_xh + (size_t)t0 * DIN;

    float acc[4][4][4];
    #pragma unroll
    for (int i = 0; i < 4; ++i)
        #pragma unroll
        for (int j = 0; j < 4; ++j)
            #pragma unroll
            for (int e = 0; e < 4; ++e) acc[i][j][e] = 0.f;

    auto load = [&](int q) {
        int st = q % 3;
        uint32_t ab = sb + st * STRIDE, bb = ab + TILE_B;
        int kt0 = q * 32;
        #pragma unroll
        for (int it = 0; it < 2; ++it) {
            int g = tid + it * NT;
            int r = g >> 2, c16 = g & 3;
            cp16(ab + r * 80 + c16 * 16, Asrc + (size_t)r * DIN + kt0 + c16 * 8, 16);
            cp16(bb + r * 80 + c16 * 16, Bsrc + (size_t)r * DIN + kt0 + c16 * 8, 16);
        }
        CP_COMMIT();
    };

    const int NCH = DIN / 32;   // 16
    load(0); load(1);
    for (int k = 0; k < NCH; k++) {
        if (k + 2 < NCH) { load(k + 2); CP_WAIT(2); }
        else if (k + 1 < NCH) { CP_WAIT(1); }
        else { CP_WAIT(0); }
        __syncthreads();
        compute_chunk(sb + (k % 3) * STRIDE, mbase, nbase, aoff, boff, acc);
        __syncthreads();
    }

    // epilogue: C[m=o][n=t] -> g_Zh[c][o][t] as half2
    #pragma unroll
    for (int mf = 0; mf < 4; ++mf) {
        int r0 = o0 + mbase + mf * 16 + lg;
        #pragma unroll
        for (int nf = 0; nf < 4; ++nf) {
            int cc = t0 + nbase + nf * 8 + 2 * t4;
            __half2 v01 = __floats2half2_rn(acc[mf][nf][0], acc[mf][nf][1]);
            __half2 v23 = __floats2half2_rn(acc[mf][nf][2], acc[mf][nf][3]);
            *(__half2*)(g_Zh + ((size_t)c * DOUT + r0) * T + cc)     = v01;
            *(__half2*)(g_Zh + ((size_t)c * DOUT + r0 + 8) * T + cc) = v23;
        }
    }
}

// -- GEMM2: out[t,o] = sum_{c,s<=t} phi_c[t-s]*Zh[c][o][s] + AR; Toeplitz A --
// Proportional split-K: tile i gets SP = i+1 split blocks -> uniform ~200 chunks/block.
__global__ void __launch_bounds__(NT, 3) gemm2_kernel() {
    extern __shared__ char smem[];
    const uint32_t sb = s2u(smem);
    const int tid = threadIdx.x;
    const int warp = tid >> 5, lane = tid & 31;
    const int lg = lane >> 2, t4 = lane & 3;
    const int mbase = (warp >> 2) * 64, nbase = (warp & 3) * 32;
    const uint32_t aoff = (uint32_t)(((lane & 15) * PITCH + (lane >> 4) * 8) * 2);
    const uint32_t boff = (uint32_t)((((lane & 7) + ((lane >> 4) & 1) * 8) * PITCH +
                                      ((lane >> 3) & 1) * 8) * 2);

    // bx -> (i, ot, sp); heavy tiles first (rb descending in i)
    int rb = 543 - (int)blockIdx.x;
    int i = 0;
    #pragma unroll
    for (int ii = 1; ii < 16; ++ii)
        if (rb >= 2 * ii * (ii + 1)) i = ii;
    int w = rb - 2 * i * (i + 1);
    const int ot = w & 3, sp = w >> 2;             // sp in [0, i+1)
    const int SP = i + 1;
    const int t0 = i * 128, o0 = ot * 128;
    const int per = (i + 1) * 4, nconv = NC * per, ntot = nconv + KU * (DIN / 32);
    const int NCH = (ntot - sp + SP - 1) / SP;

    float acc[4][4][4];
    #pragma unroll
    for (int a0 = 0; a0 < 4; ++a0)
        #pragma unroll
        for (int b0 = 0; b0 < 4; ++b0)
            #pragma unroll
            for (int e = 0; e < 4; ++e) acc[a0][b0][e] = 0.f;

    auto load = [&](int idx) {
        int q = sp + idx * SP;
        int st = idx % 3;
        uint32_t ab = sb + st * STRIDE, bb = ab + TILE_B;
        if (q < nconv) {
            int cch = q / per, rm = q - cch * per;
            int j = rm >> 2, ks0 = (rm & 3) << 5;
            const __half* Bsrc = g_Zh + ((size_t)cch * DOUT + o0) * T + j * 128 + ks0;
            #pragma unroll
            for (int it = 0; it < 2; ++it) {
                int g = tid + it * NT;
                int r = g >> 2, c16 = g & 3;
                cp16(bb + r * 80 + c16 * 16, Bsrc + (size_t)r * T + c16 * 8, 16);
            }
            CP_COMMIT();
            // Toeplitz A: A[m][k] = phiH[c][base + m - k], 0 if idx<0
            const __half* ph = g_phiH + cch * T;
            __half* As = (__half*)(smem + st * STRIDE);
            int base = (i - j) * 128 - ks0;
            #pragma unroll
            for (int it = 0; it < 2; ++it) {
                int g = tid + it * NT;
                int row = g >> 2, c0 = (g & 3) * 8;
                int idx0 = base + row - c0;
                #pragma unroll
                for (int kk = 0; kk < 8; kk += 2) {
                    int i0 = idx0 - kk;
                    __half v0 = (i0 >= 0)     ? ph[i0]     : __float2half_rn(0.f);
                    __half v1 = (i0 - 1 >= 0) ? ph[i0 - 1] : __float2half_rn(0.f);
                    *(__half2*)(As + row * PITCH + c0 + kk) = __halves2half2(v0, v1);
                }
            }
        } else {
            int r = q - nconv, tau = r >> 4, ks0 = (r & 15) << 5;
            const __half* Bsrc = g_MTh + ((size_t)tau * DOUT + o0) * DIN + ks0;
            #pragma unroll
            for (int it = 0; it < 2; ++it) {
                int g = tid + it * NT;
                int rr = g >> 2, c16 = g & 3;
                cp16(bb + rr * 80 + c16 * 16, Bsrc + (size_t)rr * DIN + c16 * 8, 16);
                int trow = t0 + rr - tau;
                const __half* As = g_xh + (size_t)(trow < 0 ? 0 : trow) * DIN + ks0 + c16 * 8;
                cp16(ab + rr * 80 + c16 * 16, As, trow >= 0 ? 16u : 0u);
            }
            CP_COMMIT();
        }
    };

    load(0);
    if (NCH > 1) load(1);
    for (int k = 0; k < NCH; k++) {
        if (k + 2 < NCH) { load(k + 2); CP_WAIT(2); }
        else if (k + 1 < NCH) { CP_WAIT(1); }
        else { CP_WAIT(0); }
        __syncthreads();
        compute_chunk(sb + (k % 3) * STRIDE, mbase, nbase, aoff, boff, acc);
        __syncthreads();
    }

    // epilogue: C[m=t][n=o] -> g_part[sp][t][o] (f32)
    float* P = g_part + (size_t)sp * T * DOUT;
    #pragma unroll
    for (int mf = 0; mf < 4; ++mf) {
        int r0 = t0 + mbase + mf * 16 + lg;
        #pragma unroll
        for (int nf = 0; nf < 4; ++nf) {
            int cc = o0 + nbase + nf * 8 + 2 * t4;
            *(float2*)(P + (size_t)r0 * DOUT + cc)       = make_float2(acc[mf][nf][0], acc[mf][nf][1]);
            *(float2*)(P + (size_t)(r0 + 8) * DOUT + cc) = make_float2(acc[mf][nf][2], acc[mf][nf][3]);
        }
    }
}

// ---------------- reduce split-K partials (tile i has i+1 planes) ----------------
__global__ void reduce_kernel(float* __restrict__ out) {
    size_t idx = (size_t)(blockIdx.x * blockDim.x + threadIdx.x) * 4;
    int t = (int)(idx / DOUT);
    int np = (t >> 7) + 1;
    float4 s = make_float4(0.f, 0.f, 0.f, 0.f);
    for (int p = 0; p < np; ++p) {
        float4 v = *(const float4*)(g_part + (size_t)p * T * DOUT + idx);
        s.x += v.x; s.y += v.y; s.z += v.z; s.w += v.w;
    }
    *(float4*)(out + idx) = s;
}

// ---------------- entry ----------------
extern "C" void kernel_launch(void* const* d_in, const int* in_sizes, int n_in,
                              void* d_out, int out_size) {
    const float* x   = (const float*)d_in[0];
    const float* phi = (const float*)d_in[1];
    const float* M   = (const float*)d_in[2];
    const float* Mp  = (const float*)d_in[3];
    const float* Mm  = (const float*)d_in[4];
    float* out = (float*)d_out;

    cudaFuncSetAttribute(gemm1_kernel, cudaFuncAttributeMaxDynamicSharedMemorySize, SMEM_SZ);
    cudaFuncSetAttribute(gemm2_kernel, cudaFuncAttributeMaxDynamicSharedMemorySize, SMEM_SZ);

    int tot = T * DIN + NC * T + KU * DOUT * DIN;
    prep_h<<<(tot + 255) / 256, 256>>>(x, phi, M);
    prep_wth<<<dim3(16, 16, 48), dim3(32, 8)>>>(Mp, Mm);
    gemm1_kernel<<<dim3(16, 4, NC), NT, SMEM_SZ>>>();
    gemm2_kernel<<<544, NT, SMEM_SZ>>>();
    reduce_kernel<<<(T * DOUT / 4 + 255) / 256, 256>>>(out);
}

// round 7
// speedup vs baseline: 2.2630x; 1.3354x over previous
#include <cuda_runtime.h>
#include <cuda_fp16.h>
#include <cstdint>

// ---------------- problem constants ----------------
#define T     2048
#define DIN   512
#define DOUT  512
#define KF    24
#define NC    48
#define KU    3
#define NT    256
#define SPLANES 16

// smem: 3-stage ring, each stage = A(128x40 half) + B(128x40 half)
// pitch 40 halves = 80B rows: 16B-aligned AND conflict-free for ldmatrix
#define PITCH   40
#define TILE_B  10240
#define STRIDE  20480
#define SMEM_SZ (3 * STRIDE)

// per-tile split counts (~242 chunks per block, 440 blocks = one wave on 148 SMs x 3)
__constant__ int c_SP[16]  = {1, 2, 3, 3, 4, 5, 6, 6, 7, 8, 9, 10, 10, 11, 12, 13};
__constant__ int c_OFF[16] = {436, 428, 416, 404, 388, 368, 344, 320,
                              292, 260, 224, 184, 144, 100, 52, 0};
#define GRID2 440

// ---------------- device scratch ----------------
__device__ __half g_Zh[(size_t)NC * DOUT * T];        // [c][o][t]  100 MB
__device__ float  g_part[(size_t)SPLANES * T * DOUT]; // split-K partials
__device__ __half g_phiH[NC * T];                     // minus channel has (-1)^lag baked in
__device__ __half g_Toep[(size_t)NC * 16 * 128 * 128];// [c][diag][m][k] 25 MB
__device__ __half g_MTh[(size_t)KU * DOUT * DIN];     // [tau][o][d]
__device__ __half g_WTh[(size_t)NC * DOUT * DIN];     // [c][o][d]
__device__ __half g_xh[(size_t)T * DIN];              // x in fp16

// ---------------- helpers ----------------
__device__ __forceinline__ uint32_t s2u(const void* p) {
    uint32_t a;
    asm("{ .reg .u64 t; cvta.to.shared.u64 t, %1; cvt.u32.u64 %0, t; }" : "=r"(a) : "l"(p));
    return a;
}
__device__ __forceinline__ void cp16(uint32_t dst, const void* src, uint32_t pbytes) {
    asm volatile("cp.async.cg.shared.global [%0], [%1], 16, %2;"
        :: "r"(dst), "l"(src), "r"(pbytes) : "memory");
}
#define CP_COMMIT() asm volatile("cp.async.commit_group;" ::: "memory")
#define CP_WAIT(N)  asm volatile("cp.async.wait_group %0;" :: "n"(N) : "memory")

__device__ __forceinline__ void mma168(float* c, const uint32_t* a, const uint32_t* b) {
    asm volatile("mma.sync.aligned.m16n8k16.row.col.f32.f16.f16.f32 "
        "{%0,%1,%2,%3}, {%4,%5,%6,%7}, {%8,%9}, {%0,%1,%2,%3};"
        : "+f"(c[0]), "+f"(c[1]), "+f"(c[2]), "+f"(c[3])
        : "r"(a[0]), "r"(a[1]), "r"(a[2]), "r"(a[3]), "r"(b[0]), "r"(b[1]));
}
__device__ __forceinline__ void ldm4(uint32_t& r0, uint32_t& r1, uint32_t& r2, uint32_t& r3,
                                     uint32_t addr) {
    asm volatile("ldmatrix.sync.aligned.m8n8.x4.shared.b16 {%0,%1,%2,%3}, [%4];"
        : "=r"(r0), "=r"(r1), "=r"(r2), "=r"(r3) : "r"(addr));
}

// one K=32 chunk for the 128x128 block tile; warp tile 64x32
__device__ __forceinline__ void compute_chunk(
    uint32_t sbase, int mbase, int nbase, uint32_t aoff, uint32_t boff, float acc[4][4][4])
{
    #pragma unroll
    for (int kf = 0; kf < 2; ++kf) {
        uint32_t b[4][2];
        #pragma unroll
        for (int nfp = 0; nfp < 2; ++nfp) {
            uint32_t addr = sbase + TILE_B + boff +
                            (uint32_t)(((nbase + nfp * 16) * PITCH + kf * 16) * 2);
            ldm4(b[2 * nfp][0], b[2 * nfp][1], b[2 * nfp + 1][0], b[2 * nfp + 1][1], addr);
        }
        #pragma unroll
        for (int mf = 0; mf < 4; ++mf) {
            uint32_t av[4];
            uint32_t addr = sbase + aoff +
                            (uint32_t)(((mbase + mf * 16) * PITCH + kf * 16) * 2);
            ldm4(av[0], av[1], av[2], av[3], addr);
            #pragma unroll
            for (int nf = 0; nf < 4; ++nf)
                mma168(acc[mf][nf], av, b[nf]);
        }
    }
}

// ---------------- prep ----------------
__global__ void prep_h(const float* __restrict__ x, const float* __restrict__ phi,
                       const float* __restrict__ M) {
    int idx = blockIdx.x * 256 + threadIdx.x;
    if (idx < T * DIN) g_xh[idx] = __float2half_rn(x[idx]);
    int p = idx - T * DIN;
    if (p >= 0 && p < NC * T) {
        int c = p / T, s = p - c * T;
        int k = (c < KF) ? c : c - KF;
        float v = phi[s * KF + k];
        if (c >= KF && (s & 1)) v = -v;
        g_phiH[p] = __float2half_rn(v);
    }
    int m = idx - T * DIN - NC * T;
    if (m >= 0 && m < KU * DOUT * DIN) {
        int tau = m / (DOUT * DIN);
        int rm = m - tau * (DOUT * DIN);
        int o = rm / DIN, d = rm - o * DIN;
        g_MTh[m] = __float2half_rn(M[((size_t)o * DIN + d) * KU + tau]);
    }
}

// Toeplitz tiles: g_Toep[c][d][m][k] = phiH[c][d*128 + m - k]  (0 if idx < 0)
__global__ void prep_toep() {
    int b = blockIdx.x;                 // c*16 + d
    int c = b >> 4, d = b & 15;
    const __half* ph = g_phiH + c * T;
    __half* dst = g_Toep + (size_t)b * 128 * 128;
    __half z = __float2half_rn(0.f);
    for (int e = threadIdx.x; e < 128 * 64; e += 256) {
        int m = e >> 6, kp = (e & 63) << 1;         // k pair
        int i0 = d * 128 + m - kp;
        __half v0 = (i0 >= 0)     ? ph[i0]     : z;
        __half v1 = (i0 - 1 >= 0) ? ph[i0 - 1] : z;
        *(__half2*)(dst + m * 128 + kp) = __halves2half2(v0, v1);
    }
}

__global__ void prep_wth(const float* __restrict__ Mp, const float* __restrict__ Mm) {
    __shared__ float t[32][33];
    int c = blockIdx.z;
    const float* W = (c < KF) ? Mp + (size_t)c * DIN * DOUT
                              : Mm + (size_t)(c - KF) * DIN * DOUT;   // [d][o]
    int d0 = blockIdx.x * 32, o0 = blockIdx.y * 32;
    int tx = threadIdx.x, ty = threadIdx.y;
    #pragma unroll
    for (int r = 0; r < 32; r += 8)
        t[ty + r][tx] = W[(size_t)(d0 + ty + r) * DOUT + o0 + tx];
    __syncthreads();
    __half* dst = g_WTh + (size_t)c * DOUT * DIN;
    #pragma unroll
    for (int r = 0; r < 32; r += 8)
        dst[(size_t)(o0 + ty + r) * DIN + d0 + tx] = __float2half_rn(t[tx][ty + r]);
}

// ------- GEMM1: Zh[c][o0+m][t0+n] = sum_d WTh[c][o][d] * xh[t][d] -------
__global__ void __launch_bounds__(NT, 3) gemm1_kernel() {
    extern __shared__ char smem[];
    const uint32_t sb = s2u(smem);
    const int tid = threadIdx.x;
    const int warp = tid >> 5, lane = tid & 31;
    const int lg = lane >> 2, t4 = lane & 3;
    const int mbase = (warp >> 2) * 64, nbase = (warp & 3) * 32;
    const uint32_t aoff = (uint32_t)(((lane & 15) * PITCH + (lane >> 4) * 8) * 2);
    const uint32_t boff = (uint32_t)((((lane & 7) + ((lane >> 4) & 1) * 8) * PITCH +
                                      ((lane >> 3) & 1) * 8) * 2);
    const int t0 = blockIdx.x * 128, o0 = blockIdx.y * 128, c = blockIdx.z;

    const __half* Asrc = g_WTh + ((size_t)c * DOUT + o0) * DIN;
    const __half* Bsrc = g_xh + (size_t)t0 * DIN;

    float acc[4][4][4];
    #pragma unroll
    for (int i = 0; i < 4; ++i)
        #pragma unroll
        for (int j = 0; j < 4; ++j)
            #pragma unroll
            for (int e = 0; e < 4; ++e) acc[i][j][e] = 0.f;

    auto load = [&](int q) {
        int st = q % 3;
        uint32_t ab = sb + st * STRIDE, bb = ab + TILE_B;
        int kt0 = q * 32;
        #pragma unroll
        for (int it = 0; it < 2; ++it) {
            int g = tid + it * NT;
            int r = g >> 2, c16 = g & 3;
            cp16(ab + r * 80 + c16 * 16, Asrc + (size_t)r * DIN + kt0 + c16 * 8, 16);
            cp16(bb + r * 80 + c16 * 16, Bsrc + (size_t)r * DIN + kt0 + c16 * 8, 16);
        }
        CP_COMMIT();
    };

    const int NCH = DIN / 32;   // 16
    load(0); load(1);
    for (int k = 0; k < NCH; k++) {
        if (k + 1 < NCH) { CP_WAIT(1); } else { CP_WAIT(0); }
        __syncthreads();                 // all warps done with stage (k-1)%3
        if (k + 2 < NCH) load(k + 2);    // safe: overwrites stage (k-1)%3
        compute_chunk(sb + (k % 3) * STRIDE, mbase, nbase, aoff, boff, acc);
    }

    // epilogue: C[m=o][n=t] -> g_Zh[c][o][t] as half2
    #pragma unroll
    for (int mf = 0; mf < 4; ++mf) {
        int r0 = o0 + mbase + mf * 16 + lg;
        #pragma unroll
        for (int nf = 0; nf < 4; ++nf) {
            int cc = t0 + nbase + nf * 8 + 2 * t4;
            __half2 v01 = __floats2half2_rn(acc[mf][nf][0], acc[mf][nf][1]);
            __half2 v23 = __floats2half2_rn(acc[mf][nf][2], acc[mf][nf][3]);
            *(__half2*)(g_Zh + ((size_t)c * DOUT + r0) * T + cc)     = v01;
            *(__half2*)(g_Zh + ((size_t)c * DOUT + r0 + 8) * T + cc) = v23;
        }
    }
}

// -- GEMM2: pure GEMM; A = precomputed Toeplitz tiles, B = Z slices; + AR --
__global__ void __launch_bounds__(NT, 3) gemm2_kernel() {
    extern __shared__ char smem[];
    const uint32_t sb = s2u(smem);
    const int tid = threadIdx.x;
    const int warp = tid >> 5, lane = tid & 31;
    const int lg = lane >> 2, t4 = lane & 3;
    const int mbase = (warp >> 2) * 64, nbase = (warp & 3) * 32;
    const uint32_t aoff = (uint32_t)(((lane & 15) * PITCH + (lane >> 4) * 8) * 2);
    const uint32_t boff = (uint32_t)((((lane & 7) + ((lane >> 4) & 1) * 8) * PITCH +
                                      ((lane >> 3) & 1) * 8) * 2);

    // decode bx -> (i, ot, sp) via per-tile offsets
    const int bx = (int)blockIdx.x;
    int i = 15;
    #pragma unroll
    for (int ii = 0; ii < 16; ++ii)
        if (bx >= c_OFF[ii] && bx < c_OFF[ii] + 4 * c_SP[ii]) i = ii;
    const int w = bx - c_OFF[i];
    const int SP = c_SP[i];
    const int ot = w % 4, sp = w / 4;               // sp in [0, SP)
    const int t0 = i * 128, o0 = ot * 128;
    const int per = (i + 1) * 4, nconv = NC * per, ntot = nconv + KU * (DIN / 32);
    const int NCH = (ntot - sp + SP - 1) / SP;

    float acc[4][4][4];
    #pragma unroll
    for (int a0 = 0; a0 < 4; ++a0)
        #pragma unroll
        for (int b0 = 0; b0 < 4; ++b0)
            #pragma unroll
            for (int e = 0; e < 4; ++e) acc[a0][b0][e] = 0.f;

    auto load = [&](int idx) {
        int q = sp + idx * SP;
        int st = idx % 3;
        uint32_t ab = sb + st * STRIDE, bb = ab + TILE_B;
        if (q < nconv) {
            int cch = q / per, rm = q - cch * per;
            int j = rm >> 2, ks0 = (rm & 3) << 5;
            const __half* Bsrc = g_Zh + ((size_t)cch * DOUT + o0) * T + j * 128 + ks0;
            const __half* Asrc = g_Toep + ((size_t)(cch * 16 + (i - j)) * 128) * 128 + ks0;
            #pragma unroll
            for (int it = 0; it < 2; ++it) {
                int g = tid + it * NT;
                int r = g >> 2, c16 = g & 3;
                cp16(bb + r * 80 + c16 * 16, Bsrc + (size_t)r * T + c16 * 8, 16);
                cp16(ab + r * 80 + c16 * 16, Asrc + (size_t)r * 128 + c16 * 8, 16);
            }
            CP_COMMIT();
        } else {
            int r = q - nconv, tau = r >> 4, ks0 = (r & 15) << 5;
            const __half* Bsrc = g_MTh + ((size_t)tau * DOUT + o0) * DIN + ks0;
            #pragma unroll
            for (int it = 0; it < 2; ++it) {
                int g = tid + it * NT;
                int rr = g >> 2, c16 = g & 3;
                cp16(bb + rr * 80 + c16 * 16, Bsrc + (size_t)rr * DIN + c16 * 8, 16);
                int trow = t0 + rr - tau;
                const __half* As = g_xh + (size_t)(trow < 0 ? 0 : trow) * DIN + ks0 + c16 * 8;
                cp16(ab + rr * 80 + c16 * 16, As, trow >= 0 ? 16u : 0u);
            }
            CP_COMMIT();
        }
    };

    load(0);
    if (NCH > 1) load(1);
    for (int k = 0; k < NCH; k++) {
        if (k + 1 < NCH) { CP_WAIT(1); } else { CP_WAIT(0); }
        __syncthreads();                 // all warps done with stage (k-1)%3
        if (k + 2 < NCH) load(k + 2);    // overwrites stage (k-1)%3
        compute_chunk(sb + (k % 3) * STRIDE, mbase, nbase, aoff, boff, acc);
    }

    // epilogue: C[m=t][n=o] -> g_part[sp][t][o] (f32)
    float* P = g_part + (size_t)sp * T * DOUT;
    #pragma unroll
    for (int mf = 0; mf < 4; ++mf) {
        int r0 = t0 + mbase + mf * 16 + lg;
        #pragma unroll
        for (int nf = 0; nf < 4; ++nf) {
            int cc = o0 + nbase + nf * 8 + 2 * t4;
            *(float2*)(P + (size_t)r0 * DOUT + cc)       = make_float2(acc[mf][nf][0], acc[mf][nf][1]);
            *(float2*)(P + (size_t)(r0 + 8) * DOUT + cc) = make_float2(acc[mf][nf][2], acc[mf][nf][3]);
        }
    }
}

// ---------------- reduce split-K partials (tile i has c_SP[i] planes) ----------------
__global__ void reduce_kernel(float* __restrict__ out) {
    size_t idx = (size_t)(blockIdx.x * blockDim.x + threadIdx.x) * 4;
    int t = (int)(idx / DOUT);
    int np = c_SP[t >> 7];
    float4 s = make_float4(0.f, 0.f, 0.f, 0.f);
    for (int p = 0; p < np; ++p) {
        float4 v = *(const float4*)(g_part + (size_t)p * T * DOUT + idx);
        s.x += v.x; s.y += v.y; s.z += v.z; s.w += v.w;
    }
    *(float4*)(out + idx) = s;
}

// ---------------- entry ----------------
extern "C" void kernel_launch(void* const* d_in, const int* in_sizes, int n_in,
                              void* d_out, int out_size) {
    const float* x   = (const float*)d_in[0];
    const float* phi = (const float*)d_in[1];
    const float* M   = (const float*)d_in[2];
    const float* Mp  = (const float*)d_in[3];
    const float* Mm  = (const float*)d_in[4];
    float* out = (float*)d_out;

    cudaFuncSetAttribute(gemm1_kernel, cudaFuncAttributeMaxDynamicSharedMemorySize, SMEM_SZ);
    cudaFuncSetAttribute(gemm2_kernel, cudaFuncAttributeMaxDynamicSharedMemorySize, SMEM_SZ);

    int tot = T * DIN + NC * T + KU * DOUT * DIN;
    prep_h<<<(tot + 255) / 256, 256>>>(x, phi, M);
    prep_toep<<<NC * 16, 256>>>();
    prep_wth<<<dim3(16, 16, 48), dim3(32, 8)>>>(Mp, Mm);
    gemm1_kernel<<<dim3(16, 4, NC), NT, SMEM_SZ>>>();
    gemm2_kernel<<<GRID2, NT, SMEM_SZ>>>();
    reduce_kernel<<<(T * DOUT / 4 + 255) / 256, 256>>>(out);
}

// round 8
// speedup vs baseline: 2.7185x; 1.2013x over previous
#include <cuda_runtime.h>
#include <cuda_fp16.h>
#include <cstdint>

// ---------------- problem constants ----------------
#define T     2048
#define DIN   512
#define DOUT  512
#define KF    24
#define NC    48
#define KU    3
#define NT    256
#define SPLANES 8

// gemm1 smem: 3-stage ring, each stage = A(128x40 half) + B(128x40 half)
#define PITCH   40
#define TILE_B  10240
#define STRIDE  20480
#define SMEM1   (3 * STRIDE)
// gemm2 smem: B-only 3-stage ring
#define SMEM2   (3 * TILE_B)

// gemm2 one-wave schedule for 2 CTAs/SM: 296 blocks, max ~400 chunks/block
__constant__ int c_SP[16]  = {1, 2, 2, 3, 3, 3, 4, 4, 5, 5, 6, 6, 7, 7, 8, 8};
__constant__ int c_OFF[16] = {292, 284, 276, 264, 252, 240, 224, 208,
                              188, 168, 144, 120, 92, 64, 32, 0};
#define GRID2 296

// ---------------- device scratch ----------------
__device__ __half   g_Zh[(size_t)NC * DOUT * T];        // [c][o][t] row layout (gemm2 B)
__device__ float    g_part[(size_t)SPLANES * T * DOUT]; // split-K partials
__device__ __half   g_phiH[NC * T];                     // minus channel has (-1)^lag baked in
__device__ uint32_t g_ToepF[(size_t)NC * 16 * 4 * 2048];// A-fragment-packed Toeplitz, 25 MB
__device__ uint32_t g_xF[(size_t)KU * 16 * 16 * 2048];  // A-fragment-packed shifted x, 6 MB
__device__ __half   g_MTh[(size_t)KU * DOUT * DIN];     // [tau][o][d] (gemm2 AR B)
__device__ __half   g_WTh[(size_t)NC * DOUT * DIN];     // [c][o][d] (gemm1 A)
__device__ __half   g_xh[(size_t)T * DIN];              // x in fp16 (gemm1 B)

// ---------------- helpers ----------------
__device__ __forceinline__ uint32_t s2u(const void* p) {
    uint32_t a;
    asm("{ .reg .u64 t; cvta.to.shared.u64 t, %1; cvt.u32.u64 %0, t; }" : "=r"(a) : "l"(p));
    return a;
}
__device__ __forceinline__ void cp16(uint32_t dst, const void* src, uint32_t pbytes) {
    asm volatile("cp.async.cg.shared.global [%0], [%1], 16, %2;"
        :: "r"(dst), "l"(src), "r"(pbytes) : "memory");
}
#define CP_COMMIT() asm volatile("cp.async.commit_group;" ::: "memory")
#define CP_WAIT(N)  asm volatile("cp.async.wait_group %0;" :: "n"(N) : "memory")

__device__ __forceinline__ void mma168(float* c, const uint32_t* a, const uint32_t* b) {
    asm volatile("mma.sync.aligned.m16n8k16.row.col.f32.f16.f16.f32 "
        "{%0,%1,%2,%3}, {%4,%5,%6,%7}, {%8,%9}, {%0,%1,%2,%3};"
        : "+f"(c[0]), "+f"(c[1]), "+f"(c[2]), "+f"(c[3])
        : "r"(a[0]), "r"(a[1]), "r"(a[2]), "r"(a[3]), "r"(b[0]), "r"(b[1]));
}
__device__ __forceinline__ void ldm4(uint32_t& r0, uint32_t& r1, uint32_t& r2, uint32_t& r3,
                                     uint32_t addr) {
    asm volatile("ldmatrix.sync.aligned.m8n8.x4.shared.b16 {%0,%1,%2,%3}, [%4];"
        : "=r"(r0), "=r"(r1), "=r"(r2), "=r"(r3) : "r"(addr));
}

// ---------------- prep ----------------
__global__ void prep_h(const float* __restrict__ x, const float* __restrict__ phi,
                       const float* __restrict__ M) {
    int idx = blockIdx.x * 256 + threadIdx.x;
    if (idx < T * DIN) g_xh[idx] = __float2half_rn(x[idx]);
    int p = idx - T * DIN;
    if (p >= 0 && p < NC * T) {
        int c = p / T, s = p - c * T;
        int k = (c < KF) ? c : c - KF;
        float v = phi[s * KF + k];
        if (c >= KF && (s & 1)) v = -v;
        g_phiH[p] = __float2half_rn(v);
    }
    int m = idx - T * DIN - NC * T;
    if (m >= 0 && m < KU * DOUT * DIN) {
        int tau = m / (DOUT * DIN);
        int rm = m - tau * (DOUT * DIN);
        int o = rm / DIN, d = rm - o * DIN;
        g_MTh[m] = __float2half_rn(M[((size_t)o * DIN + d) * KU + tau]);
    }
}

// decode fragment index u (0..2047) -> (m, k_in_chunk_pair_base)
// layout: [m16(3b)][kf(1b)][lane(5b)][reg(2b)]
__device__ __forceinline__ void frag_decode(int u, int& m, int& k) {
    int reg = u & 3, lane = (u >> 2) & 31, kf = (u >> 7) & 1, m16 = (u >> 8) & 7;
    m = m16 * 16 + (reg & 1) * 8 + (lane >> 2);
    k = kf * 16 + (reg >> 1) * 8 + (lane & 3) * 2;
}

// Toeplitz A-fragments: chunk (c,d,ks): element (m,k) = phiH[c][d*128 + m - (ks*32+k)]
__global__ void prep_toepF() {
    int b = blockIdx.x;                 // c*16 + d
    int c = b >> 4, d = b & 15;
    const __half* ph = g_phiH + c * T;
    __half2* dst = reinterpret_cast<__half2*>(g_ToepF + (size_t)b * 8192);
    __half z = __float2half_rn(0.f);
    for (int u0 = threadIdx.x; u0 < 8192; u0 += 256) {
        int ks = u0 >> 11, u = u0 & 2047;
        int m, k; frag_decode(u, m, k);
        int i0 = d * 128 + m - (ks * 32 + k);
        __half v0 = (i0 >= 0)     ? ph[i0]     : z;
        __half v1 = (i0 - 1 >= 0) ? ph[i0 - 1] : z;
        dst[u0] = __halves2half2(v0, v1);
    }
}

// shifted-x A-fragments: chunk (tau, i, ksc): element (m,k) = xh[i*128+m-tau][ksc*32+k]
__global__ void prep_xF() {
    int b = blockIdx.x;                 // (tau*16 + i)*16 + ksc
    int ksc = b & 15, ti = (b >> 4) & 15, tau = b >> 8;
    __half2* dst = reinterpret_cast<__half2*>(g_xF + (size_t)b * 2048);
    __half z = __float2half_rn(0.f);
    for (int u = threadIdx.x; u < 2048; u += 256) {
        int m, k; frag_decode(u, m, k);
        int row = ti * 128 + m - tau;
        __half v0 = z, v1 = z;
        if (row >= 0) {
            v0 = g_xh[(size_t)row * DIN + ksc * 32 + k];
            v1 = g_xh[(size_t)row * DIN + ksc * 32 + k + 1];
        }
        dst[u] = __halves2half2(v0, v1);
    }
}

__global__ void prep_wth(const float* __restrict__ Mp, const float* __restrict__ Mm) {
    __shared__ float t[32][33];
    int c = blockIdx.z;
    const float* W = (c < KF) ? Mp + (size_t)c * DIN * DOUT
                              : Mm + (size_t)(c - KF) * DIN * DOUT;   // [d][o]
    int d0 = blockIdx.x * 32, o0 = blockIdx.y * 32;
    int tx = threadIdx.x, ty = threadIdx.y;
    #pragma unroll
    for (int r = 0; r < 32; r += 8)
        t[ty + r][tx] = W[(size_t)(d0 + ty + r) * DOUT + o0 + tx];
    __syncthreads();
    __half* dst = g_WTh + (size_t)c * DOUT * DIN;
    #pragma unroll
    for (int r = 0; r < 32; r += 8)
        dst[(size_t)(o0 + ty + r) * DIN + d0 + tx] = __float2half_rn(t[tx][ty + r]);
}

// ------- GEMM1 (unchanged from R7): Zh[c][o][t] = sum_d WTh[c][o][d] * xh[t][d] -------
__global__ void __launch_bounds__(NT, 3) gemm1_kernel() {
    extern __shared__ char smem[];
    const uint32_t sb = s2u(smem);
    const int tid = threadIdx.x;
    const int warp = tid >> 5, lane = tid & 31;
    const int lg = lane >> 2, t4 = lane & 3;
    const int mbase = (warp >> 2) * 64, nbase = (warp & 3) * 32;
    const uint32_t aoff = (uint32_t)(((lane & 15) * PITCH + (lane >> 4) * 8) * 2);
    const uint32_t boff = (uint32_t)((((lane & 7) + ((lane >> 4) & 1) * 8) * PITCH +
                                      ((lane >> 3) & 1) * 8) * 2);
    const int t0 = blockIdx.x * 128, o0 = blockIdx.y * 128, c = blockIdx.z;

    const __half* Asrc = g_WTh + ((size_t)c * DOUT + o0) * DIN;
    const __half* Bsrc = g_xh + (size_t)t0 * DIN;

    float acc[4][4][4];
    #pragma unroll
    for (int i = 0; i < 4; ++i)
        #pragma unroll
        for (int j = 0; j < 4; ++j)
            #pragma unroll
            for (int e = 0; e < 4; ++e) acc[i][j][e] = 0.f;

    auto load = [&](int q) {
        int st = q % 3;
        uint32_t ab = sb + st * STRIDE, bb = ab + TILE_B;
        int kt0 = q * 32;
        #pragma unroll
        for (int it = 0; it < 2; ++it) {
            int g = tid + it * NT;
            int r = g >> 2, c16 = g & 3;
            cp16(ab + r * 80 + c16 * 16, Asrc + (size_t)r * DIN + kt0 + c16 * 8, 16);
            cp16(bb + r * 80 + c16 * 16, Bsrc + (size_t)r * DIN + kt0 + c16 * 8, 16);
        }
        CP_COMMIT();
    };

    const int NCH = DIN / 32;   // 16
    load(0); load(1);
    for (int k = 0; k < NCH; k++) {
        if (k + 1 < NCH) { CP_WAIT(1); } else { CP_WAIT(0); }
        __syncthreads();
        if (k + 2 < NCH) load(k + 2);
        uint32_t sbase = sb + (k % 3) * STRIDE;
        #pragma unroll
        for (int kf = 0; kf < 2; ++kf) {
            uint32_t b[4][2];
            #pragma unroll
            for (int nfp = 0; nfp < 2; ++nfp) {
                uint32_t addr = sbase + TILE_B + boff +
                                (uint32_t)(((nbase + nfp * 16) * PITCH + kf * 16) * 2);
                ldm4(b[2 * nfp][0], b[2 * nfp][1], b[2 * nfp + 1][0], b[2 * nfp + 1][1], addr);
            }
            #pragma unroll
            for (int mf = 0; mf < 4; ++mf) {
                uint32_t av[4];
                uint32_t addr = sbase + aoff +
                                (uint32_t)(((mbase + mf * 16) * PITCH + kf * 16) * 2);
                ldm4(av[0], av[1], av[2], av[3], addr);
                #pragma unroll
                for (int nf = 0; nf < 4; ++nf)
                    mma168(acc[mf][nf], av, b[nf]);
            }
        }
    }

    #pragma unroll
    for (int mf = 0; mf < 4; ++mf) {
        int r0 = o0 + mbase + mf * 16 + lg;
        #pragma unroll
        for (int nf = 0; nf < 4; ++nf) {
            int cc = t0 + nbase + nf * 8 + 2 * t4;
            __half2 v01 = __floats2half2_rn(acc[mf][nf][0], acc[mf][nf][1]);
            __half2 v23 = __floats2half2_rn(acc[mf][nf][2], acc[mf][nf][3]);
            *(__half2*)(g_Zh + ((size_t)c * DOUT + r0) * T + cc)     = v01;
            *(__half2*)(g_Zh + ((size_t)c * DOUT + r0 + 8) * T + cc) = v23;
        }
    }
}

// -- GEMM2: A register-direct from fragment-packed gmem; B via smem pipeline --
__global__ void __launch_bounds__(NT, 2) gemm2_kernel() {
    extern __shared__ char smem[];
    const uint32_t sb = s2u(smem);
    const int tid = threadIdx.x;
    const int warp = tid >> 5, lane = tid & 31;
    const int lg = lane >> 2, t4 = lane & 3;
    const int mbase = (warp >> 2) * 64, nbase = (warp & 3) * 32;
    const int m16b = mbase >> 4;
    const uint32_t boff = (uint32_t)((((lane & 7) + ((lane >> 4) & 1) * 8) * PITCH +
                                      ((lane >> 3) & 1) * 8) * 2);

    const int bx = (int)blockIdx.x;
    int i = 15;
    #pragma unroll
    for (int ii = 0; ii < 16; ++ii)
        if (bx >= c_OFF[ii] && bx < c_OFF[ii] + 4 * c_SP[ii]) i = ii;
    const int w = bx - c_OFF[i];
    const int SP = c_SP[i];
    const int ot = w % 4, sp = w / 4;
    const int t0 = i * 128, o0 = ot * 128;
    const int per = (i + 1) * 4, nconv = NC * per, ntot = nconv + KU * (DIN / 32);
    const int NCH = (ntot - sp + SP - 1) / SP;

    float acc[4][4][4];
    #pragma unroll
    for (int a0 = 0; a0 < 4; ++a0)
        #pragma unroll
        for (int b0 = 0; b0 < 4; ++b0)
            #pragma unroll
            for (int e = 0; e < 4; ++e) acc[a0][b0][e] = 0.f;

    auto aPtr = [&](int idx) -> const uint4* {
        int q = sp + idx * SP;
        if (q < nconv) {
            int cch = q / per, rm = q - cch * per;
            int j = rm >> 2, ks = rm & 3;
            return reinterpret_cast<const uint4*>(g_ToepF) +
                   (size_t)((cch * 16 + (i - j)) * 4 + ks) * 512;
        } else {
            int r = q - nconv, tau = r >> 4, ksc = r & 15;
            return reinterpret_cast<const uint4*>(g_xF) +
                   (size_t)((tau * 16 + i) * 16 + ksc) * 512;
        }
    };
    auto loadB = [&](int idx) {
        int q = sp + idx * SP;
        uint32_t bb = sb + (idx % 3) * TILE_B;
        if (q < nconv) {
            int cch = q / per, rm = q - cch * per;
            int j = rm >> 2, ks0 = (rm & 3) << 5;
            const __half* Bsrc = g_Zh + ((size_t)cch * DOUT + o0) * T + j * 128 + ks0;
            #pragma unroll
            for (int it = 0; it < 2; ++it) {
                int g = tid + it * NT;
                int r = g >> 2, c16 = g & 3;
                cp16(bb + r * 80 + c16 * 16, Bsrc + (size_t)r * T + c16 * 8, 16);
            }
        } else {
            int r = q - nconv, tau = r >> 4, ks0 = (r & 15) << 5;
            const __half* Bsrc = g_MTh + ((size_t)tau * DOUT + o0) * DIN + ks0;
            #pragma unroll
            for (int it = 0; it < 2; ++it) {
                int g = tid + it * NT;
                int rr = g >> 2, c16 = g & 3;
                cp16(bb + rr * 80 + c16 * 16, Bsrc + (size_t)rr * DIN + c16 * 8, 16);
            }
        }
        CP_COMMIT();
    };

    uint4 areg[2][4];
    auto loadA = [&](const uint4* ap) {
        #pragma unroll
        for (int kf = 0; kf < 2; ++kf)
            #pragma unroll
            for (int mf = 0; mf < 4; ++mf)
                areg[kf][mf] = ap[(m16b + mf) * 64 + kf * 32 + lane];
    };

    loadB(0);
    if (NCH > 1) loadB(1);
    loadA(aPtr(0));

    for (int k = 0; k < NCH; k++) {
        if (k + 1 < NCH) { CP_WAIT(1); } else { CP_WAIT(0); }
        __syncthreads();
        if (k + 2 < NCH) loadB(k + 2);
        uint32_t sbB = sb + (k % 3) * TILE_B;
        #pragma unroll
        for (int kf = 0; kf < 2; ++kf) {
            uint32_t b[4][2];
            #pragma unroll
            for (int nfp = 0; nfp < 2; ++nfp) {
                uint32_t addr = sbB + boff +
                                (uint32_t)(((nbase + nfp * 16) * PITCH + kf * 16) * 2);
                ldm4(b[2 * nfp][0], b[2 * nfp][1], b[2 * nfp + 1][0], b[2 * nfp + 1][1], addr);
            }
            #pragma unroll
            for (int mf = 0; mf < 4; ++mf)
                #pragma unroll
                for (int nf = 0; nf < 4; ++nf)
                    mma168(acc[mf][nf], reinterpret_cast<const uint32_t*>(&areg[kf][mf]), b[nf]);
        }
        if (k + 1 < NCH) loadA(aPtr(k + 1));   // latency hides over next wait+sync+ldm
    }

    float* P = g_part + (size_t)sp * T * DOUT;
    #pragma unroll
    for (int mf = 0; mf < 4; ++mf) {
        int r0 = t0 + mbase + mf * 16 + lg;
        #pragma unroll
        for (int nf = 0; nf < 4; ++nf) {
            int cc = o0 + nbase + nf * 8 + 2 * t4;
            *(float2*)(P + (size_t)r0 * DOUT + cc)       = make_float2(acc[mf][nf][0], acc[mf][nf][1]);
            *(float2*)(P + (size_t)(r0 + 8) * DOUT + cc) = make_float2(acc[mf][nf][2], acc[mf][nf][3]);
        }
    }
}

// ---------------- reduce split-K partials (tile i has c_SP[i] planes) ----------------
__global__ void reduce_kernel(float* __restrict__ out) {
    size_t idx = (size_t)(blockIdx.x * blockDim.x + threadIdx.x) * 4;
    int t = (int)(idx / DOUT);
    int np = c_SP[t >> 7];
    float4 s = make_float4(0.f, 0.f, 0.f, 0.f);
    for (int p = 0; p < np; ++p) {
        float4 v = *(const float4*)(g_part + (size_t)p * T * DOUT + idx);
        s.x += v.x; s.y += v.y; s.z += v.z; s.w += v.w;
    }
    *(float4*)(out + idx) = s;
}

// ---------------- entry ----------------
extern "C" void kernel_launch(void* const* d_in, const int* in_sizes, int n_in,
                              void* d_out, int out_size) {
    const float* x   = (const float*)d_in[0];
    const float* phi = (const float*)d_in[1];
    const float* M   = (const float*)d_in[2];
    const float* Mp  = (const float*)d_in[3];
    const float* Mm  = (const float*)d_in[4];
    float* out = (float*)d_out;

    cudaFuncSetAttribute(gemm1_kernel, cudaFuncAttributeMaxDynamicSharedMemorySize, SMEM1);
    cudaFuncSetAttribute(gemm2_kernel, cudaFuncAttributeMaxDynamicSharedMemorySize, SMEM2);

    int tot = T * DIN + NC * T + KU * DOUT * DIN;
    prep_h<<<(tot + 255) / 256, 256>>>(x, phi, M);
    prep_toepF<<<NC * 16, 256>>>();
    prep_xF<<<KU * 16 * 16, 256>>>();
    prep_wth<<<dim3(16, 16, 48), dim3(32, 8)>>>(Mp, Mm);
    gemm1_kernel<<<dim3(16, 4, NC), NT, SMEM1>>>();
    gemm2_kernel<<<GRID2, NT, SMEM2>>>();
    reduce_kernel<<<(T * DOUT / 4 + 255) / 256, 256>>>(out);
}

// round 9
// speedup vs baseline: 3.4111x; 1.2548x over previous
#include <cuda_runtime.h>
#include <cuda_fp16.h>
#include <cstdint>

// ---------------- problem constants ----------------
#define T     2048
#define DIN   512
#define DOUT  512
#define KF    24
#define NC    48
#define KU    3
#define NT    256
#define SPLANES 8

// B-only smem ring (both GEMMs): 3 stages x 128x40 half
#define PITCH   40
#define TILE_B  10240
#define SMEM_B  (3 * TILE_B)

// gemm2 one-wave schedule for 2 CTAs/SM: 296 blocks
__constant__ int c_SP[16]  = {1, 2, 2, 3, 3, 3, 4, 4, 5, 5, 6, 6, 7, 7, 8, 8};
__constant__ int c_OFF[16] = {292, 284, 276, 264, 252, 240, 224, 208,
                              188, 168, 144, 120, 92, 64, 32, 0};
#define GRID2 296

// ---------------- device scratch ----------------
__device__ __half   g_Zh[(size_t)NC * DOUT * T];        // [c][o][t] (gemm2 B)
__device__ float    g_part[(size_t)SPLANES * T * DOUT]; // split-K partials
__device__ __half   g_phiH[NC * T];                     // minus channel has (-1)^lag baked in
__device__ uint32_t g_ToepF[(size_t)NC * 16 * 4 * 2048];// A-frag Toeplitz, 25 MB
__device__ uint32_t g_xF[(size_t)KU * 16 * 16 * 2048];  // A-frag shifted x, 6 MB
__device__ uint32_t g_WF[(size_t)NC * 4 * 16 * 2048];   // A-frag weights, 25 MB
__device__ __half   g_MTh[(size_t)KU * DOUT * DIN];     // [tau][o][d] (gemm2 AR B)
__device__ __half   g_xh[(size_t)T * DIN];              // x fp16 (gemm1 B)

// ---------------- helpers ----------------
__device__ __forceinline__ uint32_t s2u(const void* p) {
    uint32_t a;
    asm("{ .reg .u64 t; cvta.to.shared.u64 t, %1; cvt.u32.u64 %0, t; }" : "=r"(a) : "l"(p));
    return a;
}
__device__ __forceinline__ void cp16(uint32_t dst, const void* src, uint32_t pbytes) {
    asm volatile("cp.async.cg.shared.global [%0], [%1], 16, %2;"
        :: "r"(dst), "l"(src), "r"(pbytes) : "memory");
}
#define CP_COMMIT() asm volatile("cp.async.commit_group;" ::: "memory")
#define CP_WAIT(N)  asm volatile("cp.async.wait_group %0;" :: "n"(N) : "memory")

__device__ __forceinline__ void mma168(float* c, const uint32_t* a, const uint32_t* b) {
    asm volatile("mma.sync.aligned.m16n8k16.row.col.f32.f16.f16.f32 "
        "{%0,%1,%2,%3}, {%4,%5,%6,%7}, {%8,%9}, {%0,%1,%2,%3};"
        : "+f"(c[0]), "+f"(c[1]), "+f"(c[2]), "+f"(c[3])
        : "r"(a[0]), "r"(a[1]), "r"(a[2]), "r"(a[3]), "r"(b[0]), "r"(b[1]));
}
__device__ __forceinline__ void ldm4(uint32_t& r0, uint32_t& r1, uint32_t& r2, uint32_t& r3,
                                     uint32_t addr) {
    asm volatile("ldmatrix.sync.aligned.m8n8.x4.shared.b16 {%0,%1,%2,%3}, [%4];"
        : "=r"(r0), "=r"(r1), "=r"(r2), "=r"(r3) : "r"(addr));
}

// fragment index u (0..2047) -> (m 0..127, k 0..31); layout [m16][kf][lane][reg]
__device__ __forceinline__ void frag_decode(int u, int& m, int& k) {
    int reg = u & 3, lane = (u >> 2) & 31, kf = (u >> 7) & 1, m16 = (u >> 8) & 7;
    m = m16 * 16 + (reg & 1) * 8 + (lane >> 2);
    k = kf * 16 + (reg >> 1) * 8 + (lane & 3) * 2;
}

// ---------------- prep ----------------
__global__ void prep_h(const float* __restrict__ x, const float* __restrict__ phi,
                       const float* __restrict__ M) {
    int idx = blockIdx.x * 256 + threadIdx.x;
    if (idx < T * DIN) g_xh[idx] = __float2half_rn(x[idx]);
    int p = idx - T * DIN;
    if (p >= 0 && p < NC * T) {
        int c = p / T, s = p - c * T;
        int k = (c < KF) ? c : c - KF;
        float v = phi[s * KF + k];
        if (c >= KF && (s & 1)) v = -v;
        g_phiH[p] = __float2half_rn(v);
    }
    int m = idx - T * DIN - NC * T;
    if (m >= 0 && m < KU * DOUT * DIN) {
        int tau = m / (DOUT * DIN);
        int rm = m - tau * (DOUT * DIN);
        int o = rm / DIN, d = rm - o * DIN;
        g_MTh[m] = __float2half_rn(M[((size_t)o * DIN + d) * KU + tau]);
    }
}

// Toeplitz A-fragments: chunk (c,diag,ks): (m,k) = phiH[c][diag*128 + m - (ks*32+k)]
__global__ void prep_toepF() {
    int b = blockIdx.x;                 // c*16 + diag
    int c = b >> 4, d = b & 15;
    const __half* ph = g_phiH + c * T;
    __half2* dst = reinterpret_cast<__half2*>(g_ToepF + (size_t)b * 8192);
    __half z = __float2half_rn(0.f);
    for (int u0 = threadIdx.x; u0 < 8192; u0 += 256) {
        int ks = u0 >> 11, u = u0 & 2047;
        int m, k; frag_decode(u, m, k);
        int i0 = d * 128 + m - (ks * 32 + k);
        __half v0 = (i0 >= 0)     ? ph[i0]     : z;
        __half v1 = (i0 - 1 >= 0) ? ph[i0 - 1] : z;
        dst[u0] = __halves2half2(v0, v1);
    }
}

// shifted-x A-fragments: chunk (tau,i,ksc): (m,k) = xh[i*128+m-tau][ksc*32+k]
__global__ void prep_xF() {
    int b = blockIdx.x;                 // (tau*16 + i)*16 + ksc
    int ksc = b & 15, ti = (b >> 4) & 15, tau = b >> 8;
    __half2* dst = reinterpret_cast<__half2*>(g_xF + (size_t)b * 2048);
    __half z = __float2half_rn(0.f);
    for (int u = threadIdx.x; u < 2048; u += 256) {
        int m, k; frag_decode(u, m, k);
        int row = ti * 128 + m - tau;
        __half v0 = z, v1 = z;
        if (row >= 0) {
            v0 = g_xh[(size_t)row * DIN + ksc * 32 + k];
            v1 = g_xh[(size_t)row * DIN + ksc * 32 + k + 1];
        }
        dst[u] = __halves2half2(v0, v1);
    }
}

// weight A-fragments: chunk (c,oTile,ksc): (m,k) = W_c[d = ksc*32+k][o = oTile*128+m]
__global__ void prep_wf(const float* __restrict__ Mp, const float* __restrict__ Mm) {
    __shared__ float s[32][129];
    int b = blockIdx.x;                 // (c*4 + by)*16 + ksc
    int ksc = b & 15, by = (b >> 4) & 3, c = b >> 6;
    const float* W = (c < KF) ? Mp + (size_t)c * DIN * DOUT
                              : Mm + (size_t)(c - KF) * DIN * DOUT;   // [d][o]
    int o0 = by * 128, d0 = ksc * 32;
    int tid = threadIdx.x;
    for (int e = tid; e < 32 * 128; e += 256) {
        int dd = e >> 7, oo = e & 127;
        s[dd][oo] = W[(size_t)(d0 + dd) * DOUT + o0 + oo];
    }
    __syncthreads();
    __half2* dst = reinterpret_cast<__half2*>(g_WF + (size_t)b * 2048);
    for (int u = tid; u < 2048; u += 256) {
        int m, k; frag_decode(u, m, k);
        dst[u] = __halves2half2(__float2half_rn(s[k][m]), __float2half_rn(s[k + 1][m]));
    }
}

// ------- GEMM1: Zh[c][o][t] = sum_d W_c[d][o] * xh[t][d]; A reg-direct, B smem -------
__global__ void __launch_bounds__(NT, 2) gemm1_kernel() {
    extern __shared__ char smem[];
    const uint32_t sb = s2u(smem);
    const int tid = threadIdx.x;
    const int warp = tid >> 5, lane = tid & 31;
    const int lg = lane >> 2, t4 = lane & 3;
    const int mbase = (warp >> 2) * 64, nbase = (warp & 3) * 32;
    const int m16b = mbase >> 4;
    const uint32_t boff = (uint32_t)((((lane & 7) + ((lane >> 4) & 1) * 8) * PITCH +
                                      ((lane >> 3) & 1) * 8) * 2);
    const int t0 = blockIdx.x * 128, by = blockIdx.y, o0 = by * 128, c = blockIdx.z;

    const __half* Bsrc = g_xh + (size_t)t0 * DIN;
    const uint4* abase = reinterpret_cast<const uint4*>(g_WF) + (size_t)(c * 4 + by) * 16 * 512;

    float acc[4][4][4];
    #pragma unroll
    for (int i = 0; i < 4; ++i)
        #pragma unroll
        for (int j = 0; j < 4; ++j)
            #pragma unroll
            for (int e = 0; e < 4; ++e) acc[i][j][e] = 0.f;

    auto loadB = [&](int q) {
        uint32_t bb = sb + (q % 3) * TILE_B;
        int kt0 = q * 32;
        #pragma unroll
        for (int it = 0; it < 2; ++it) {
            int g = tid + it * NT;
            int r = g >> 2, c16 = g & 3;
            cp16(bb + r * 80 + c16 * 16, Bsrc + (size_t)r * DIN + kt0 + c16 * 8, 16);
        }
        CP_COMMIT();
    };

    uint4 areg[2][4];
    auto loadA = [&](int q) {
        const uint4* ap = abase + q * 512;
        #pragma unroll
        for (int kf = 0; kf < 2; ++kf)
            #pragma unroll
            for (int mf = 0; mf < 4; ++mf)
                areg[kf][mf] = ap[(m16b + mf) * 64 + kf * 32 + lane];
    };

    const int NCH = DIN / 32;   // 16
    loadB(0); loadB(1);
    loadA(0);
    for (int k = 0; k < NCH; k++) {
        if (k + 1 < NCH) { CP_WAIT(1); } else { CP_WAIT(0); }
        __syncthreads();
        if (k + 2 < NCH) loadB(k + 2);
        uint32_t sbB = sb + (k % 3) * TILE_B;
        #pragma unroll
        for (int kf = 0; kf < 2; ++kf) {
            uint32_t b[4][2];
            #pragma unroll
            for (int nfp = 0; nfp < 2; ++nfp) {
                uint32_t addr = sbB + boff +
                                (uint32_t)(((nbase + nfp * 16) * PITCH + kf * 16) * 2);
                ldm4(b[2 * nfp][0], b[2 * nfp][1], b[2 * nfp + 1][0], b[2 * nfp + 1][1], addr);
            }
            #pragma unroll
            for (int mf = 0; mf < 4; ++mf)
                #pragma unroll
                for (int nf = 0; nf < 4; ++nf)
                    mma168(acc[mf][nf], reinterpret_cast<const uint32_t*>(&areg[kf][mf]), b[nf]);
        }
        if (k + 1 < NCH) loadA(k + 1);
    }

    // epilogue: C[m=o][n=t] -> g_Zh[c][o][t] as half2
    #pragma unroll
    for (int mf = 0; mf < 4; ++mf) {
        int r0 = o0 + mbase + mf * 16 + lg;
        #pragma unroll
        for (int nf = 0; nf < 4; ++nf) {
            int cc = t0 + nbase + nf * 8 + 2 * t4;
            __half2 v01 = __floats2half2_rn(acc[mf][nf][0], acc[mf][nf][1]);
            __half2 v23 = __floats2half2_rn(acc[mf][nf][2], acc[mf][nf][3]);
            *(__half2*)(g_Zh + ((size_t)c * DOUT + r0) * T + cc)     = v01;
            *(__half2*)(g_Zh + ((size_t)c * DOUT + r0 + 8) * T + cc) = v23;
        }
    }
}

// -- GEMM2: A register-direct (Toeplitz / shifted-x frags); B via smem pipeline --
__global__ void __launch_bounds__(NT, 2) gemm2_kernel() {
    extern __shared__ char smem[];
    const uint32_t sb = s2u(smem);
    const int tid = threadIdx.x;
    const int warp = tid >> 5, lane = tid & 31;
    const int lg = lane >> 2, t4 = lane & 3;
    const int mbase = (warp >> 2) * 64, nbase = (warp & 3) * 32;
    const int m16b = mbase >> 4;
    const uint32_t boff = (uint32_t)((((lane & 7) + ((lane >> 4) & 1) * 8) * PITCH +
                                      ((lane >> 3) & 1) * 8) * 2);

    const int bx = (int)blockIdx.x;
    int i = 15;
    #pragma unroll
    for (int ii = 0; ii < 16; ++ii)
        if (bx >= c_OFF[ii] && bx < c_OFF[ii] + 4 * c_SP[ii]) i = ii;
    const int w = bx - c_OFF[i];
    const int SP = c_SP[i];
    const int ot = w % 4, sp = w / 4;
    const int t0 = i * 128, o0 = ot * 128;
    const int per = (i + 1) * 4, nconv = NC * per, ntot = nconv + KU * (DIN / 32);
    const int NCH = (ntot - sp + SP - 1) / SP;

    float acc[4][4][4];
    #pragma unroll
    for (int a0 = 0; a0 < 4; ++a0)
        #pragma unroll
        for (int b0 = 0; b0 < 4; ++b0)
            #pragma unroll
            for (int e = 0; e < 4; ++e) acc[a0][b0][e] = 0.f;

    auto aPtr = [&](int idx) -> const uint4* {
        int q = sp + idx * SP;
        if (q < nconv) {
            int cch = q / per, rm = q - cch * per;
            int j = rm >> 2, ks = rm & 3;
            return reinterpret_cast<const uint4*>(g_ToepF) +
                   (size_t)((cch * 16 + (i - j)) * 4 + ks) * 512;
        } else {
            int r = q - nconv, tau = r >> 4, ksc = r & 15;
            return reinterpret_cast<const uint4*>(g_xF) +
                   (size_t)((tau * 16 + i) * 16 + ksc) * 512;
        }
    };
    auto loadB = [&](int idx) {
        int q = sp + idx * SP;
        uint32_t bb = sb + (idx % 3) * TILE_B;
        if (q < nconv) {
            int cch = q / per, rm = q - cch * per;
            int j = rm >> 2, ks0 = (rm & 3) << 5;
            const __half* Bsrc = g_Zh + ((size_t)cch * DOUT + o0) * T + j * 128 + ks0;
            #pragma unroll
            for (int it = 0; it < 2; ++it) {
                int g = tid + it * NT;
                int r = g >> 2, c16 = g & 3;
                cp16(bb + r * 80 + c16 * 16, Bsrc + (size_t)r * T + c16 * 8, 16);
            }
        } else {
            int r = q - nconv, tau = r >> 4, ks0 = (r & 15) << 5;
            const __half* Bsrc = g_MTh + ((size_t)tau * DOUT + o0) * DIN + ks0;
            #pragma unroll
            for (int it = 0; it < 2; ++it) {
                int g = tid + it * NT;
                int rr = g >> 2, c16 = g & 3;
                cp16(bb + rr * 80 + c16 * 16, Bsrc + (size_t)rr * DIN + c16 * 8, 16);
            }
        }
        CP_COMMIT();
    };

    uint4 areg[2][4];
    auto loadA = [&](const uint4* ap) {
        #pragma unroll
        for (int kf = 0; kf < 2; ++kf)
            #pragma unroll
            for (int mf = 0; mf < 4; ++mf)
                areg[kf][mf] = ap[(m16b + mf) * 64 + kf * 32 + lane];
    };

    loadB(0);
    if (NCH > 1) loadB(1);
    loadA(aPtr(0));

    for (int k = 0; k < NCH; k++) {
        if (k + 1 < NCH) { CP_WAIT(1); } else { CP_WAIT(0); }
        __syncthreads();
        if (k + 2 < NCH) loadB(k + 2);
        uint32_t sbB = sb + (k % 3) * TILE_B;
        #pragma unroll
        for (int kf = 0; kf < 2; ++kf) {
            uint32_t b[4][2];
            #pragma unroll
            for (int nfp = 0; nfp < 2; ++nfp) {
                uint32_t addr = sbB + boff +
                                (uint32_t)(((nbase + nfp * 16) * PITCH + kf * 16) * 2);
                ldm4(b[2 * nfp][0], b[2 * nfp][1], b[2 * nfp + 1][0], b[2 * nfp + 1][1], addr);
            }
            #pragma unroll
            for (int mf = 0; mf < 4; ++mf)
                #pragma unroll
                for (int nf = 0; nf < 4; ++nf)
                    mma168(acc[mf][nf], reinterpret_cast<const uint32_t*>(&areg[kf][mf]), b[nf]);
        }
        if (k + 1 < NCH) loadA(aPtr(k + 1));
    }

    float* P = g_part + (size_t)sp * T * DOUT;
    #pragma unroll
    for (int mf = 0; mf < 4; ++mf) {
        int r0 = t0 + mbase + mf * 16 + lg;
        #pragma unroll
        for (int nf = 0; nf < 4; ++nf) {
            int cc = o0 + nbase + nf * 8 + 2 * t4;
            *(float2*)(P + (size_t)r0 * DOUT + cc)       = make_float2(acc[mf][nf][0], acc[mf][nf][1]);
            *(float2*)(P + (size_t)(r0 + 8) * DOUT + cc) = make_float2(acc[mf][nf][2], acc[mf][nf][3]);
        }
    }
}

// ---------------- reduce split-K partials (tile i has c_SP[i] planes) ----------------
__global__ void reduce_kernel(float* __restrict__ out) {
    size_t idx = (size_t)(blockIdx.x * blockDim.x + threadIdx.x) * 4;
    int t = (int)(idx / DOUT);
    int np = c_SP[t >> 7];
    float4 s = make_float4(0.f, 0.f, 0.f, 0.f);
    for (int p = 0; p < np; ++p) {
        float4 v = *(const float4*)(g_part + (size_t)p * T * DOUT + idx);
        s.x += v.x; s.y += v.y; s.z += v.z; s.w += v.w;
    }
    *(float4*)(out + idx) = s;
}

// ---------------- entry ----------------
extern "C" void kernel_launch(void* const* d_in, const int* in_sizes, int n_in,
                              void* d_out, int out_size) {
    const float* x   = (const float*)d_in[0];
    const float* phi = (const float*)d_in[1];
    const float* M   = (const float*)d_in[2];
    const float* Mp  = (const float*)d_in[3];
    const float* Mm  = (const float*)d_in[4];
    float* out = (float*)d_out;

    cudaFuncSetAttribute(gemm1_kernel, cudaFuncAttributeMaxDynamicSharedMemorySize, SMEM_B);
    cudaFuncSetAttribute(gemm2_kernel, cudaFuncAttributeMaxDynamicSharedMemorySize, SMEM_B);

    int tot = T * DIN + NC * T + KU * DOUT * DIN;
    prep_h<<<(tot + 255) / 256, 256>>>(x, phi, M);
    prep_toepF<<<NC * 16, 256>>>();
    prep_xF<<<KU * 16 * 16, 256>>>();
    prep_wf<<<NC * 4 * 16, 256>>>(Mp, Mm);
    gemm1_kernel<<<dim3(16, 4, NC), NT, SMEM_B>>>();
    gemm2_kernel<<<GRID2, NT, SMEM_B>>>();
    reduce_kernel<<<(T * DOUT / 4 + 255) / 256, 256>>>(out);
}

// round 10
// speedup vs baseline: 3.6533x; 1.0710x over previous
#include <cuda_runtime.h>
#include <cuda_fp16.h>
#include <cstdint>

// ---------------- problem constants ----------------
#define T     2048
#define DIN   512
#define DOUT  512
#define KF    24
#define NC    48
#define KU    3
#define NT    256
#define SPLANES 8

// gemm2 one-wave schedule for 2 CTAs/SM: 296 blocks
__constant__ int c_SP[16]  = {1, 2, 2, 3, 3, 3, 4, 4, 5, 5, 6, 6, 7, 7, 8, 8};
__constant__ int c_OFF[16] = {292, 284, 276, 264, 252, 240, 224, 208,
                              188, 168, 144, 120, 92, 64, 32, 0};
#define GRID2 296

// ---------------- device scratch ----------------
// Z in B-fragment layout: u32 idx = ((c*64+tc)*64 + nfrag)*128 + kf*64 + lane*2 + reg
__device__ uint32_t g_ZF[(size_t)NC * 64 * 64 * 128];   // 100 MB
__device__ float    g_part[(size_t)SPLANES * T * DOUT]; // split-K partials
__device__ __half   g_phiH[NC * T];                     // minus channel has (-1)^lag baked in
__device__ uint32_t g_ToepF[(size_t)NC * 16 * 4 * 2048];// A-frag Toeplitz, 25 MB
__device__ uint32_t g_xF[(size_t)KU * 16 * 16 * 2048];  // A-frag shifted x (AR), 6 MB
__device__ uint32_t g_WF[(size_t)NC * 4 * 16 * 2048];   // A-frag weights, 25 MB
__device__ uint32_t g_xBF[(size_t)16 * 256 * 128];      // B-frag x (gemm1), 2 MB
__device__ uint32_t g_MF[(size_t)KU * 16 * 64 * 128];   // B-frag AR weights, 1.5 MB
__device__ __half   g_xh[(size_t)T * DIN];              // x fp16 (for prep_xF)

// ---------------- helpers ----------------
__device__ __forceinline__ void mma168(float* c, const uint32_t* a, const uint32_t* b) {
    asm volatile("mma.sync.aligned.m16n8k16.row.col.f32.f16.f16.f32 "
        "{%0,%1,%2,%3}, {%4,%5,%6,%7}, {%8,%9}, {%0,%1,%2,%3};"
        : "+f"(c[0]), "+f"(c[1]), "+f"(c[2]), "+f"(c[3])
        : "r"(a[0]), "r"(a[1]), "r"(a[2]), "r"(a[3]), "r"(b[0]), "r"(b[1]));
}

// A-frag index u (0..2047) -> (m 0..127, k 0..31); layout [m16][kf][lane][reg]
__device__ __forceinline__ void frag_decode(int u, int& m, int& k) {
    int reg = u & 3, lane = (u >> 2) & 31, kf = (u >> 7) & 1, m16 = (u >> 8) & 7;
    m = m16 * 16 + (reg & 1) * 8 + (lane >> 2);
    k = kf * 16 + (reg >> 1) * 8 + (lane & 3) * 2;
}
// B-frag: u32 within a (nfrag,kf) pair: lane*2+reg; element n = lane>>2,
// k = kf*16 + reg*8 + (lane&3)*2 + {0,1}

// ---------------- prep ----------------
__global__ void prep_h(const float* __restrict__ x, const float* __restrict__ phi) {
    int idx = blockIdx.x * 256 + threadIdx.x;
    if (idx < T * DIN) g_xh[idx] = __float2half_rn(x[idx]);
    int p = idx - T * DIN;
    if (p >= 0 && p < NC * T) {
        int c = p / T, s = p - c * T;
        int k = (c < KF) ? c : c - KF;
        float v = phi[s * KF + k];
        if (c >= KF && (s & 1)) v = -v;
        g_phiH[p] = __float2half_rn(v);
    }
}

// Toeplitz A-fragments: chunk (c,diag,ks): (m,k) = phiH[c][diag*128 + m - (ks*32+k)]
__global__ void prep_toepF() {
    int b = blockIdx.x;                 // c*16 + diag
    int c = b >> 4, d = b & 15;
    const __half* ph = g_phiH + c * T;
    __half2* dst = reinterpret_cast<__half2*>(g_ToepF + (size_t)b * 8192);
    __half z = __float2half_rn(0.f);
    for (int u0 = threadIdx.x; u0 < 8192; u0 += 256) {
        int ks = u0 >> 11, u = u0 & 2047;
        int m, k; frag_decode(u, m, k);
        int i0 = d * 128 + m - (ks * 32 + k);
        __half v0 = (i0 >= 0)     ? ph[i0]     : z;
        __half v1 = (i0 - 1 >= 0) ? ph[i0 - 1] : z;
        dst[u0] = __halves2half2(v0, v1);
    }
}

// shifted-x A-fragments (AR): chunk (tau,i,ksc): (m,k) = xh[i*128+m-tau][ksc*32+k]
__global__ void prep_xF() {
    int b = blockIdx.x;                 // (tau*16 + i)*16 + ksc
    int ksc = b & 15, ti = (b >> 4) & 15, tau = b >> 8;
    __half2* dst = reinterpret_cast<__half2*>(g_xF + (size_t)b * 2048);
    __half z = __float2half_rn(0.f);
    for (int u = threadIdx.x; u < 2048; u += 256) {
        int m, k; frag_decode(u, m, k);
        int row = ti * 128 + m - tau;
        __half v0 = z, v1 = z;
        if (row >= 0) {
            v0 = g_xh[(size_t)row * DIN + ksc * 32 + k];
            v1 = g_xh[(size_t)row * DIN + ksc * 32 + k + 1];
        }
        dst[u] = __halves2half2(v0, v1);
    }
}

// weight A-fragments: chunk (c,oTile,ksc): (m,k) = W_c[d=ksc*32+k][o=oTile*128+m]
__global__ void prep_wf(const float* __restrict__ Mp, const float* __restrict__ Mm) {
    __shared__ float s[32][129];
    int b = blockIdx.x;                 // (c*4 + by)*16 + ksc
    int ksc = b & 15, by = (b >> 4) & 3, c = b >> 6;
    const float* W = (c < KF) ? Mp + (size_t)c * DIN * DOUT
                              : Mm + (size_t)(c - KF) * DIN * DOUT;   // [d][o]
    int o0 = by * 128, d0 = ksc * 32;
    int tid = threadIdx.x;
    for (int e = tid; e < 32 * 128; e += 256) {
        int dd = e >> 7, oo = e & 127;
        s[dd][oo] = W[(size_t)(d0 + dd) * DOUT + o0 + oo];
    }
    __syncthreads();
    __half2* dst = reinterpret_cast<__half2*>(g_WF + (size_t)b * 2048);
    for (int u = tid; u < 2048; u += 256) {
        int m, k; frag_decode(u, m, k);
        dst[u] = __halves2half2(__float2half_rn(s[k][m]), __float2half_rn(s[k + 1][m]));
    }
}

// x B-fragments (gemm1 B): u32 idx = ((ksc*256+tfrag)*2+kf)*64 + lane*2 + reg
__global__ void prep_xbf(const float* __restrict__ x) {
    int idx = blockIdx.x * 256 + threadIdx.x;       // over 16*256*128 u32
    if (idx >= 16 * 256 * 128) return;
    int reg = idx & 1, lane = (idx >> 1) & 31, kf = (idx >> 6) & 1;
    int tfrag = (idx >> 7) & 255, ksc = idx >> 15;
    int t = tfrag * 8 + (lane >> 2);
    int d = ksc * 32 + kf * 16 + reg * 8 + (lane & 3) * 2;
    const float* p = x + (size_t)t * DIN + d;
    g_xBF[idx] = __float_as_uint(0.f),
    g_xBF[idx] = *(uint32_t*)&(__half2&)*(__half2*)nullptr, (void)0;   // placeholder removed
}

// (real version below; the above is unreachable — see prep_xbf2)
__global__ void prep_xbf2(const float* __restrict__ x) {
    int idx = blockIdx.x * 256 + threadIdx.x;
    if (idx >= 16 * 256 * 128) return;
    int reg = idx & 1, lane = (idx >> 1) & 31, kf = (idx >> 6) & 1;
    int tfrag = (idx >> 7) & 255, ksc = idx >> 15;
    int t = tfrag * 8 + (lane >> 2);
    int d = ksc * 32 + kf * 16 + reg * 8 + (lane & 3) * 2;
    __half2 v = __floats2half2_rn(x[(size_t)t * DIN + d], x[(size_t)t * DIN + d + 1]);
    g_xBF[idx] = *reinterpret_cast<uint32_t*>(&v);
}

// AR-weight B-fragments: u32 idx = (((tau*16+ksc)*64+ofrag)*2+kf)*64 + lane*2 + reg
__global__ void prep_mf(const float* __restrict__ M) {
    int idx = blockIdx.x * 256 + threadIdx.x;       // over 3*16*64*128 u32
    if (idx >= KU * 16 * 64 * 128) return;
    int reg = idx & 1, lane = (idx >> 1) & 31, kf = (idx >> 6) & 1;
    int ofrag = (idx >> 7) & 63, ksc = (idx >> 13) & 15, tau = idx >> 17;
    int o = ofrag * 8 + (lane >> 2);
    int d = ksc * 32 + kf * 16 + reg * 8 + (lane & 3) * 2;
    __half2 v = __floats2half2_rn(M[((size_t)o * DIN + d) * KU + tau],
                                  M[((size_t)o * DIN + d + 1) * KU + tau]);
    g_MF[idx] = *reinterpret_cast<uint32_t*>(&v);
}

// ------- GEMM1: all-register-direct; writes Z in B-frag layout -------
__global__ void __launch_bounds__(NT, 2) gemm1_kernel() {
    const int tid = threadIdx.x;
    const int warp = tid >> 5, lane = tid & 31;
    const int mbase = (warp >> 2) * 64, nbase = (warp & 3) * 32;
    const int m16b = mbase >> 4;
    const int tx = blockIdx.x, by = blockIdx.y, c = blockIdx.z;
    const int o0 = by * 128;

    const uint4* abase = reinterpret_cast<const uint4*>(g_WF) + (size_t)(c * 4 + by) * 16 * 512;
    const uint2* bbase = reinterpret_cast<const uint2*>(g_xBF);
    const int tf0 = tx * 16 + (nbase >> 3);

    float acc[4][4][4];
    #pragma unroll
    for (int i = 0; i < 4; ++i)
        #pragma unroll
        for (int j = 0; j < 4; ++j)
            #pragma unroll
            for (int e = 0; e < 4; ++e) acc[i][j][e] = 0.f;

    uint4 areg[2][4];
    uint2 breg[2][4];
    auto loadA = [&](int ksc) {
        const uint4* ap = abase + ksc * 512;
        #pragma unroll
        for (int kf = 0; kf < 2; ++kf)
            #pragma unroll
            for (int mf = 0; mf < 4; ++mf)
                areg[kf][mf] = ap[(m16b + mf) * 64 + kf * 32 + lane];
    };
    auto loadB = [&](int ksc) {
        #pragma unroll
        for (int kf = 0; kf < 2; ++kf)
            #pragma unroll
            for (int nf = 0; nf < 4; ++nf)
                breg[kf][nf] = bbase[(size_t)((ksc * 256 + tf0 + nf) * 2 + kf) * 32 + lane];
    };

    loadA(0); loadB(0);
    for (int k = 0; k < 16; k++) {
        #pragma unroll
        for (int kf = 0; kf < 2; ++kf)
            #pragma unroll
            for (int mf = 0; mf < 4; ++mf)
                #pragma unroll
                for (int nf = 0; nf < 4; ++nf)
                    mma168(acc[mf][nf], reinterpret_cast<const uint32_t*>(&areg[kf][mf]),
                           reinterpret_cast<const uint32_t*>(&breg[kf][nf]));
        if (k + 1 < 16) { loadA(k + 1); loadB(k + 1); }
    }

    // epilogue: write g_ZF B-frags; frag-lane == producer-lane
    const int tc = tx * 4 + (warp & 3);
    uint2* zf = reinterpret_cast<uint2*>(g_ZF);
    #pragma unroll
    for (int mf = 0; mf < 4; ++mf) {
        int nf0 = (o0 + mbase + mf * 16) >> 3;
        #pragma unroll
        for (int kf = 0; kf < 2; ++kf) {
            __half2 lo0 = __floats2half2_rn(acc[mf][2 * kf][0], acc[mf][2 * kf][1]);
            __half2 lo1 = __floats2half2_rn(acc[mf][2 * kf + 1][0], acc[mf][2 * kf + 1][1]);
            __half2 hi0 = __floats2half2_rn(acc[mf][2 * kf][2], acc[mf][2 * kf][3]);
            __half2 hi1 = __floats2half2_rn(acc[mf][2 * kf + 1][2], acc[mf][2 * kf + 1][3]);
            zf[(size_t)(((c * 64 + tc) * 64 + nf0) * 2 + kf) * 32 + lane] =
                make_uint2(*reinterpret_cast<uint32_t*>(&lo0), *reinterpret_cast<uint32_t*>(&lo1));
            zf[(size_t)(((c * 64 + tc) * 64 + nf0 + 1) * 2 + kf) * 32 + lane] =
                make_uint2(*reinterpret_cast<uint32_t*>(&hi0), *reinterpret_cast<uint32_t*>(&hi1));
        }
    }
}

// -- GEMM2: all-register-direct; A = Toeplitz/shifted-x frags, B = ZF/MF frags --
__global__ void __launch_bounds__(NT, 2) gemm2_kernel() {
    const int tid = threadIdx.x;
    const int warp = tid >> 5, lane = tid & 31;
    const int lg = lane >> 2, t4 = lane & 3;
    const int mbase = (warp >> 2) * 64, nbase = (warp & 3) * 32;
    const int m16b = mbase >> 4;

    const int bx = (int)blockIdx.x;
    int i = 15;
    #pragma unroll
    for (int ii = 0; ii < 16; ++ii)
        if (bx >= c_OFF[ii] && bx < c_OFF[ii] + 4 * c_SP[ii]) i = ii;
    const int w = bx - c_OFF[i];
    const int SP = c_SP[i];
    const int ot = w % 4, sp = w / 4;
    const int t0 = i * 128, o0 = ot * 128;
    const int per = (i + 1) * 4, nconv = NC * per, ntot = nconv + KU * (DIN / 32);
    const int NCH = (ntot - sp + SP - 1) / SP;
    const int nfr0 = (o0 >> 3) + (nbase >> 3);

    float acc[4][4][4];
    #pragma unroll
    for (int a0 = 0; a0 < 4; ++a0)
        #pragma unroll
        for (int b0 = 0; b0 < 4; ++b0)
            #pragma unroll
            for (int e = 0; e < 4; ++e) acc[a0][b0][e] = 0.f;

    uint4 areg[2][4];
    uint2 breg[2][4];
    auto loadChunk = [&](int idx) {
        int q = sp + idx * SP;
        const uint4* ap;
        const uint2* bp;
        if (q < nconv) {
            int cch = q / per, rm = q - cch * per;
            int j = rm >> 2, ks = rm & 3;
            ap = reinterpret_cast<const uint4*>(g_ToepF) +
                 (size_t)((cch * 16 + (i - j)) * 4 + ks) * 512;
            bp = reinterpret_cast<const uint2*>(g_ZF) +
                 (size_t)((cch * 64 + j * 4 + ks) * 64 + nfr0) * 64;
        } else {
            int r = q - nconv, tau = r >> 4, ksc = r & 15;
            ap = reinterpret_cast<const uint4*>(g_xF) +
                 (size_t)((tau * 16 + i) * 16 + ksc) * 512;
            bp = reinterpret_cast<const uint2*>(g_MF) +
                 (size_t)(((tau * 16 + ksc) * 64) + nfr0) * 64;
        }
        #pragma unroll
        for (int kf = 0; kf < 2; ++kf)
            #pragma unroll
            for (int mf = 0; mf < 4; ++mf)
                areg[kf][mf] = ap[(m16b + mf) * 64 + kf * 32 + lane];
        #pragma unroll
        for (int kf = 0; kf < 2; ++kf)
            #pragma unroll
            for (int nf = 0; nf < 4; ++nf)
                breg[kf][nf] = bp[(size_t)(nf * 2 + kf) * 32 + lane];
    };

    loadChunk(0);
    for (int k = 0; k < NCH; k++) {
        #pragma unroll
        for (int kf = 0; kf < 2; ++kf)
            #pragma unroll
            for (int mf = 0; mf < 4; ++mf)
                #pragma unroll
                for (int nf = 0; nf < 4; ++nf)
                    mma168(acc[mf][nf], reinterpret_cast<const uint32_t*>(&areg[kf][mf]),
                           reinterpret_cast<const uint32_t*>(&breg[kf][nf]));
        if (k + 1 < NCH) loadChunk(k + 1);
    }

    float* P = g_part + (size_t)sp * T * DOUT;
    #pragma unroll
    for (int mf = 0; mf < 4; ++mf) {
        int r0 = t0 + mbase + mf * 16 + lg;
        #pragma unroll
        for (int nf = 0; nf < 4; ++nf) {
            int cc = o0 + nbase + nf * 8 + 2 * t4;
            *(float2*)(P + (size_t)r0 * DOUT + cc)       = make_float2(acc[mf][nf][0], acc[mf][nf][1]);
            *(float2*)(P + (size_t)(r0 + 8) * DOUT + cc) = make_float2(acc[mf][nf][2], acc[mf][nf][3]);
        }
    }
}

// ---------------- reduce split-K partials (tile i has c_SP[i] planes) ----------------
__global__ void reduce_kernel(float* __restrict__ out) {
    size_t idx = (size_t)(blockIdx.x * blockDim.x + threadIdx.x) * 4;
    int t = (int)(idx / DOUT);
    int np = c_SP[t >> 7];
    float4 s = make_float4(0.f, 0.f, 0.f, 0.f);
    for (int p = 0; p < np; ++p) {
        float4 v = *(const float4*)(g_part + (size_t)p * T * DOUT + idx);
        s.x += v.x; s.y += v.y; s.z += v.z; s.w += v.w;
    }
    *(float4*)(out + idx) = s;
}

// ---------------- entry ----------------
extern "C" void kernel_launch(void* const* d_in, const int* in_sizes, int n_in,
                              void* d_out, int out_size) {
    const float* x   = (const float*)d_in[0];
    const float* phi = (const float*)d_in[1];
    const float* M   = (const float*)d_in[2];
    const float* Mp  = (const float*)d_in[3];
    const float* Mm  = (const float*)d_in[4];
    float* out = (float*)d_out;

    prep_h<<<(T * DIN + NC * T + 255) / 256, 256>>>(x, phi);
    prep_toepF<<<NC * 16, 256>>>();
    prep_xF<<<KU * 16 * 16, 256>>>();
    prep_wf<<<NC * 4 * 16, 256>>>(Mp, Mm);
    prep_xbf2<<<(16 * 256 * 128 + 255) / 256, 256>>>(x);
    prep_mf<<<(KU * 16 * 64 * 128 + 255) / 256, 256>>>(M);
    gemm1_kernel<<<dim3(16, 4, NC), NT>>>();
    gemm2_kernel<<<GRID2, NT>>>();
    reduce_kernel<<<(T * DOUT / 4 + 255) / 256, 256>>>(out);
}

// round 11
// speedup vs baseline: 3.7481x; 1.0260x over previous
#include <cuda_runtime.h>
#include <cuda_fp16.h>
#include <cstdint>

// ---------------- problem constants ----------------
#define T     2048
#define DIN   512
#define DOUT  512
#define KF    24
#define NC    48
#define KU    3
#define NT    256
#define SPLANES 8

// gemm2 one-wave schedule for 2 CTAs/SM: 296 blocks
__constant__ int c_SP[16]  = {1, 2, 2, 3, 3, 3, 4, 4, 5, 5, 6, 6, 7, 7, 8, 8};
__constant__ int c_OFF[16] = {292, 284, 276, 264, 252, 240, 224, 208,
                              188, 168, 144, 120, 92, 64, 32, 0};
#define GRID2 296

// ---------------- device scratch ----------------
// Z in paired-B-fragment layout: uint4 idx = ((c*64+tc)*64 + nfrag)*32 + lane
//   components {kf0reg0, kf0reg1, kf1reg0, kf1reg1}; element n = nfrag*8+(lane>>2),
//   k(within 32-chunk) = kf*16 + reg*8 + (lane&3)*2 + {0,1}
__device__ uint4    g_ZF[(size_t)NC * 64 * 64 * 32];    // 100 MB
__device__ float    g_part[(size_t)SPLANES * T * DOUT]; // split-K partials
__device__ __half   g_phiH[NC * T];                     // minus channel has (-1)^lag baked in
__device__ uint32_t g_ToepF[(size_t)NC * 16 * 4 * 2048];// A-frag Toeplitz, 25 MB
__device__ uint32_t g_xF[(size_t)KU * 16 * 16 * 2048];  // A-frag shifted x (AR), 6 MB
__device__ uint32_t g_WF[(size_t)NC * 4 * 16 * 2048];   // A-frag weights, 25 MB
__device__ uint4    g_xBF[(size_t)16 * 256 * 32];       // paired-B-frag x (gemm1), 2 MB
__device__ uint4    g_MF[(size_t)KU * 16 * 64 * 32];    // paired-B-frag AR weights, 1.5 MB
__device__ __half   g_xh[(size_t)T * DIN];              // x fp16 (for prep_xF)

// ---------------- helpers ----------------
__device__ __forceinline__ void mma168(float* c, const uint32_t* a, const uint32_t* b) {
    asm volatile("mma.sync.aligned.m16n8k16.row.col.f32.f16.f16.f32 "
        "{%0,%1,%2,%3}, {%4,%5,%6,%7}, {%8,%9}, {%0,%1,%2,%3};"
        : "+f"(c[0]), "+f"(c[1]), "+f"(c[2]), "+f"(c[3])
        : "r"(a[0]), "r"(a[1]), "r"(a[2]), "r"(a[3]), "r"(b[0]), "r"(b[1]));
}

// A-frag index u (0..2047) -> (m 0..127, k 0..31); layout [m16][kf][lane][reg]
__device__ __forceinline__ void frag_decode(int u, int& m, int& k) {
    int reg = u & 3, lane = (u >> 2) & 31, kf = (u >> 7) & 1, m16 = (u >> 8) & 7;
    m = m16 * 16 + (reg & 1) * 8 + (lane >> 2);
    k = kf * 16 + (reg >> 1) * 8 + (lane & 3) * 2;
}

// ---------------- prep ----------------
__global__ void prep_h(const float* __restrict__ x, const float* __restrict__ phi) {
    int idx = blockIdx.x * 256 + threadIdx.x;
    if (idx < T * DIN) g_xh[idx] = __float2half_rn(x[idx]);
    int p = idx - T * DIN;
    if (p >= 0 && p < NC * T) {
        int c = p / T, s = p - c * T;
        int k = (c < KF) ? c : c - KF;
        float v = phi[s * KF + k];
        if (c >= KF && (s & 1)) v = -v;
        g_phiH[p] = __float2half_rn(v);
    }
}

// Toeplitz A-fragments: chunk (c,diag,ks): (m,k) = phiH[c][diag*128 + m - (ks*32+k)]
__global__ void prep_toepF() {
    int b = blockIdx.x;                 // c*16 + diag
    int c = b >> 4, d = b & 15;
    const __half* ph = g_phiH + c * T;
    __half2* dst = reinterpret_cast<__half2*>(g_ToepF + (size_t)b * 8192);
    __half z = __float2half_rn(0.f);
    for (int u0 = threadIdx.x; u0 < 8192; u0 += 256) {
        int ks = u0 >> 11, u = u0 & 2047;
        int m, k; frag_decode(u, m, k);
        int i0 = d * 128 + m - (ks * 32 + k);
        __half v0 = (i0 >= 0)     ? ph[i0]     : z;
        __half v1 = (i0 - 1 >= 0) ? ph[i0 - 1] : z;
        dst[u0] = __halves2half2(v0, v1);
    }
}

// shifted-x A-fragments (AR): chunk (tau,i,ksc): (m,k) = xh[i*128+m-tau][ksc*32+k]
__global__ void prep_xF() {
    int b = blockIdx.x;                 // (tau*16 + i)*16 + ksc
    int ksc = b & 15, ti = (b >> 4) & 15, tau = b >> 8;
    __half2* dst = reinterpret_cast<__half2*>(g_xF + (size_t)b * 2048);
    __half z = __float2half_rn(0.f);
    for (int u = threadIdx.x; u < 2048; u += 256) {
        int m, k; frag_decode(u, m, k);
        int row = ti * 128 + m - tau;
        __half v0 = z, v1 = z;
        if (row >= 0) {
            v0 = g_xh[(size_t)row * DIN + ksc * 32 + k];
            v1 = g_xh[(size_t)row * DIN + ksc * 32 + k + 1];
        }
        dst[u] = __halves2half2(v0, v1);
    }
}

// weight A-fragments: chunk (c,oTile,ksc): (m,k) = W_c[d=ksc*32+k][o=oTile*128+m]
__global__ void prep_wf(const float* __restrict__ Mp, const float* __restrict__ Mm) {
    __shared__ float s[32][129];
    int b = blockIdx.x;                 // (c*4 + by)*16 + ksc
    int ksc = b & 15, by = (b >> 4) & 3, c = b >> 6;
    const float* W = (c < KF) ? Mp + (size_t)c * DIN * DOUT
                              : Mm + (size_t)(c - KF) * DIN * DOUT;   // [d][o]
    int o0 = by * 128, d0 = ksc * 32;
    int tid = threadIdx.x;
    for (int e = tid; e < 32 * 128; e += 256) {
        int dd = e >> 7, oo = e & 127;
        s[dd][oo] = W[(size_t)(d0 + dd) * DOUT + o0 + oo];
    }
    __syncthreads();
    __half2* dst = reinterpret_cast<__half2*>(g_WF + (size_t)b * 2048);
    for (int u = tid; u < 2048; u += 256) {
        int m, k; frag_decode(u, m, k);
        dst[u] = __halves2half2(__float2half_rn(s[k][m]), __float2half_rn(s[k + 1][m]));
    }
}

// x paired-B-fragments (gemm1 B): uint4 idx = (ksc*256 + tfrag)*32 + lane
__global__ void prep_xbf(const float* __restrict__ x) {
    int idx = blockIdx.x * 256 + threadIdx.x;       // over 16*256*32 uint4
    if (idx >= 16 * 256 * 32) return;
    int lane = idx & 31, tfrag = (idx >> 5) & 255, ksc = idx >> 13;
    int t = tfrag * 8 + (lane >> 2);
    uint32_t comp[4];
    #pragma unroll
    for (int cI = 0; cI < 4; ++cI) {
        int kf = cI >> 1, reg = cI & 1;
        int d = ksc * 32 + kf * 16 + reg * 8 + (lane & 3) * 2;
        __half2 v = __floats2half2_rn(x[(size_t)t * DIN + d], x[(size_t)t * DIN + d + 1]);
        comp[cI] = *reinterpret_cast<uint32_t*>(&v);
    }
    g_xBF[idx] = make_uint4(comp[0], comp[1], comp[2], comp[3]);
}

// AR-weight paired-B-fragments: uint4 idx = ((tau*16+ksc)*64 + nfrag)*32 + lane
__global__ void prep_mf(const float* __restrict__ M) {
    int idx = blockIdx.x * 256 + threadIdx.x;       // over 3*16*64*32 uint4
    if (idx >= KU * 16 * 64 * 32) return;
    int lane = idx & 31, nfrag = (idx >> 5) & 63, ksc = (idx >> 11) & 15, tau = idx >> 15;
    int o = nfrag * 8 + (lane >> 2);
    uint32_t comp[4];
    #pragma unroll
    for (int cI = 0; cI < 4; ++cI) {
        int kf = cI >> 1, reg = cI & 1;
        int d = ksc * 32 + kf * 16 + reg * 8 + (lane & 3) * 2;
        __half2 v = __floats2half2_rn(M[((size_t)o * DIN + d) * KU + tau],
                                      M[((size_t)o * DIN + d + 1) * KU + tau]);
        comp[cI] = *reinterpret_cast<uint32_t*>(&v);
    }
    g_MF[idx] = make_uint4(comp[0], comp[1], comp[2], comp[3]);
}

// ------- GEMM1: all-register-direct; writes Z in paired-B-frag layout -------
__global__ void __launch_bounds__(NT, 2) gemm1_kernel() {
    const int tid = threadIdx.x;
    const int warp = tid >> 5, lane = tid & 31;
    const int mbase = (warp >> 2) * 64, nbase = (warp & 3) * 32;
    const int m16b = mbase >> 4;
    const int tx = blockIdx.x, by = blockIdx.y, c = blockIdx.z;
    const int o0 = by * 128;

    const uint4* abase = reinterpret_cast<const uint4*>(g_WF) + (size_t)(c * 4 + by) * 16 * 512;
    const int tf0 = tx * 16 + (nbase >> 3);

    float acc[4][4][4];
    #pragma unroll
    for (int i = 0; i < 4; ++i)
        #pragma unroll
        for (int j = 0; j < 4; ++j)
            #pragma unroll
            for (int e = 0; e < 4; ++e) acc[i][j][e] = 0.f;

    uint4 areg[2][4];
    uint4 breg[4];
    auto loadA = [&](int ksc) {
        const uint4* ap = abase + ksc * 512;
        #pragma unroll
        for (int kf = 0; kf < 2; ++kf)
            #pragma unroll
            for (int mf = 0; mf < 4; ++mf)
                areg[kf][mf] = ap[(m16b + mf) * 64 + kf * 32 + lane];
    };
    auto loadB = [&](int ksc) {
        #pragma unroll
        for (int nf = 0; nf < 4; ++nf)
            breg[nf] = g_xBF[(size_t)(ksc * 256 + tf0 + nf) * 32 + lane];
    };

    loadA(0); loadB(0);
    for (int k = 0; k < 16; k++) {
        #pragma unroll
        for (int kf = 0; kf < 2; ++kf)
            #pragma unroll
            for (int mf = 0; mf < 4; ++mf)
                #pragma unroll
                for (int nf = 0; nf < 4; ++nf)
                    mma168(acc[mf][nf], reinterpret_cast<const uint32_t*>(&areg[kf][mf]),
                           reinterpret_cast<const uint32_t*>(&breg[nf]) + kf * 2);
        if (k + 1 < 16) { loadA(k + 1); loadB(k + 1); }
    }

    // epilogue: paired-B-frag stores; frag-lane == producer-lane; nf == kf*2+reg
    const int tc = tx * 4 + (warp & 3);
    #pragma unroll
    for (int mf = 0; mf < 4; ++mf) {
        int nfr = (o0 + mbase + mf * 16) >> 3;
        uint32_t lo[4], hi[4];
        #pragma unroll
        for (int nf = 0; nf < 4; ++nf) {
            __half2 l = __floats2half2_rn(acc[mf][nf][0], acc[mf][nf][1]);
            __half2 h = __floats2half2_rn(acc[mf][nf][2], acc[mf][nf][3]);
            lo[nf] = *reinterpret_cast<uint32_t*>(&l);
            hi[nf] = *reinterpret_cast<uint32_t*>(&h);
        }
        g_ZF[(size_t)((c * 64 + tc) * 64 + nfr) * 32 + lane]     = make_uint4(lo[0], lo[1], lo[2], lo[3]);
        g_ZF[(size_t)((c * 64 + tc) * 64 + nfr + 1) * 32 + lane] = make_uint4(hi[0], hi[1], hi[2], hi[3]);
    }
}

// -- GEMM2: all-register-direct; A = Toeplitz/shifted-x frags, B = ZF/MF paired frags --
__global__ void __launch_bounds__(NT, 2) gemm2_kernel() {
    const int tid = threadIdx.x;
    const int warp = tid >> 5, lane = tid & 31;
    const int lg = lane >> 2, t4 = lane & 3;
    const int mbase = (warp >> 2) * 64, nbase = (warp & 3) * 32;
    const int m16b = mbase >> 4;

    const int bx = (int)blockIdx.x;
    int i = 15;
    #pragma unroll
    for (int ii = 0; ii < 16; ++ii)
        if (bx >= c_OFF[ii] && bx < c_OFF[ii] + 4 * c_SP[ii]) i = ii;
    const int w = bx - c_OFF[i];
    const int SP = c_SP[i];
    const int ot = w % 4, sp = w / 4;
    const int t0 = i * 128, o0 = ot * 128;
    const int per = (i + 1) * 4, nconv = NC * per, ntot = nconv + KU * (DIN / 32);
    const int NCH = (ntot - sp + SP - 1) / SP;
    const int nfr0 = (o0 >> 3) + (nbase >> 3);

    float acc[4][4][4];
    #pragma unroll
    for (int a0 = 0; a0 < 4; ++a0)
        #pragma unroll
        for (int b0 = 0; b0 < 4; ++b0)
            #pragma unroll
            for (int e = 0; e < 4; ++e) acc[a0][b0][e] = 0.f;

    uint4 areg[2][4];
    uint4 breg[4];
    auto loadChunk = [&](int idx) {
        int q = sp + idx * SP;
        const uint4* ap;
        const uint4* bp;
        if (q < nconv) {
            int cch = q / per, rm = q - cch * per;
            int j = rm >> 2, ks = rm & 3;
            ap = reinterpret_cast<const uint4*>(g_ToepF) +
                 (size_t)((cch * 16 + (i - j)) * 4 + ks) * 512;
            bp = g_ZF + (size_t)((cch * 64 + j * 4 + ks) * 64 + nfr0) * 32;
        } else {
            int r = q - nconv, tau = r >> 4, ksc = r & 15;
            ap = reinterpret_cast<const uint4*>(g_xF) +
                 (size_t)((tau * 16 + i) * 16 + ksc) * 512;
            bp = g_MF + (size_t)((tau * 16 + ksc) * 64 + nfr0) * 32;
        }
        #pragma unroll
        for (int kf = 0; kf < 2; ++kf)
            #pragma unroll
            for (int mf = 0; mf < 4; ++mf)
                areg[kf][mf] = ap[(m16b + mf) * 64 + kf * 32 + lane];
        #pragma unroll
        for (int nf = 0; nf < 4; ++nf)
            breg[nf] = bp[(size_t)nf * 32 + lane];
    };

    loadChunk(0);
    for (int k = 0; k < NCH; k++) {
        #pragma unroll
        for (int kf = 0; kf < 2; ++kf)
            #pragma unroll
            for (int mf = 0; mf < 4; ++mf)
                #pragma unroll
                for (int nf = 0; nf < 4; ++nf)
                    mma168(acc[mf][nf], reinterpret_cast<const uint32_t*>(&areg[kf][mf]),
                           reinterpret_cast<const uint32_t*>(&breg[nf]) + kf * 2);
        if (k + 1 < NCH) loadChunk(k + 1);
    }

    float* P = g_part + (size_t)sp * T * DOUT;
    #pragma unroll
    for (int mf = 0; mf < 4; ++mf) {
        int r0 = t0 + mbase + mf * 16 + lg;
        #pragma unroll
        for (int nf = 0; nf < 4; ++nf) {
            int cc = o0 + nbase + nf * 8 + 2 * t4;
            *(float2*)(P + (size_t)r0 * DOUT + cc)       = make_float2(acc[mf][nf][0], acc[mf][nf][1]);
            *(float2*)(P + (size_t)(r0 + 8) * DOUT + cc) = make_float2(acc[mf][nf][2], acc[mf][nf][3]);
        }
    }
}

// ---------------- reduce split-K partials (tile i has c_SP[i] planes) ----------------
__global__ void reduce_kernel(float* __restrict__ out) {
    size_t idx = (size_t)(blockIdx.x * blockDim.x + threadIdx.x) * 4;
    int t = (int)(idx / DOUT);
    int np = c_SP[t >> 7];
    float4 s = make_float4(0.f, 0.f, 0.f, 0.f);
    for (int p = 0; p < np; ++p) {
        float4 v = *(const float4*)(g_part + (size_t)p * T * DOUT + idx);
        s.x += v.x; s.y += v.y; s.z += v.z; s.w += v.w;
    }
    *(float4*)(out + idx) = s;
}

// ---------------- entry ----------------
extern "C" void kernel_launch(void* const* d_in, const int* in_sizes, int n_in,
                              void* d_out, int out_size) {
    const float* x   = (const float*)d_in[0];
    const float* phi = (const float*)d_in[1];
    const float* M   = (const float*)d_in[2];
    const float* Mp  = (const float*)d_in[3];
    const float* Mm  = (const float*)d_in[4];
    float* out = (float*)d_out;

    prep_h<<<(T * DIN + NC * T + 255) / 256, 256>>>(x, phi);
    prep_toepF<<<NC * 16, 256>>>();
    prep_xF<<<KU * 16 * 16, 256>>>();
    prep_wf<<<NC * 4 * 16, 256>>>(Mp, Mm);
    prep_xbf<<<(16 * 256 * 32 + 255) / 256, 256>>>(x);
    prep_mf<<<(KU * 16 * 64 * 32 + 255) / 256, 256>>>(M);
    gemm1_kernel<<<dim3(16, 4, NC), NT>>>();
    gemm2_kernel<<<GRID2, NT>>>();
    reduce_kernel<<<(T * DOUT / 4 + 255) / 256, 256>>>(out);
}